// round 1
// baseline (speedup 1.0000x reference)
#include <cuda_runtime.h>

#define B_   2
#define N_   2048
#define E_   1024
#define H_   16
#define HD_  64
#define M_   (B_*N_)        // 4096 rows total
#define QKVC (H_*3*HD_)     // 3072 qkv columns

// Scratch (static __device__ — no allocations allowed)
__device__ float g_q [B_*H_*N_*HD_];
__device__ float g_k [B_*H_*N_*HD_];
__device__ float g_v [B_*H_*N_*HD_];
__device__ float g_sa[B_*N_*E_];

// ---------------------------------------------------------------------------
// Kernel 1: per-head QKV projection.
// C[m, c] = sum_e X[m, e] * Wqkv[h, e, f] + bqkv[c],  c = h*192 + f
// Split order (reference): f<64 -> K, f<128 -> Q, else V. Scatter to [B,H,N,HD].
// 128x128 tile, BK=8, 8x8 per thread, 256 threads.
// ---------------------------------------------------------------------------
__global__ __launch_bounds__(256) void qkv_gemm_kernel(
    const float* __restrict__ X, const float* __restrict__ W,
    const float* __restrict__ bias)
{
    __shared__ float As[8][128];   // A transposed: As[k][m]
    __shared__ float Bs[8][128];
    const int tid = threadIdx.x;
    const int m0 = blockIdx.y * 128;
    const int n0 = blockIdx.x * 128;
    const int tr = tid >> 4, tc = tid & 15;

    float acc[8][8];
#pragma unroll
    for (int i = 0; i < 8; i++)
#pragma unroll
        for (int j = 0; j < 8; j++) acc[i][j] = 0.f;

    const int aRow = tid >> 1;          // 0..127
    const int aSeg = (tid & 1) * 4;     // 0 or 4
    const int bRow = tid >> 5;          // 0..7
    const int bCol = (tid & 31) * 4;    // 0..124
    const int colg = n0 + bCol;
    const int hb = colg / 192;
    const int fb = colg - hb * 192;     // f%4==0, chunk of 4 stays in one head
    const float* Bbase = W + (size_t)hb * (E_ * 192) + fb;
    const float* Abase = X + (size_t)(m0 + aRow) * E_ + aSeg;

    for (int k0 = 0; k0 < E_; k0 += 8) {
        float4 a4 = *(const float4*)(Abase + k0);
        As[aSeg + 0][aRow] = a4.x;
        As[aSeg + 1][aRow] = a4.y;
        As[aSeg + 2][aRow] = a4.z;
        As[aSeg + 3][aRow] = a4.w;
        float4 b4 = *(const float4*)(Bbase + (size_t)(k0 + bRow) * 192);
        *(float4*)(&Bs[bRow][bCol]) = b4;
        __syncthreads();
#pragma unroll
        for (int kk = 0; kk < 8; kk++) {
            float a[8], b[8];
            *(float4*)&a[0] = *(const float4*)&As[kk][tr * 8];
            *(float4*)&a[4] = *(const float4*)&As[kk][tr * 8 + 4];
            *(float4*)&b[0] = *(const float4*)&Bs[kk][tc * 8];
            *(float4*)&b[4] = *(const float4*)&Bs[kk][tc * 8 + 4];
#pragma unroll
            for (int i = 0; i < 8; i++)
#pragma unroll
                for (int j = 0; j < 8; j++) acc[i][j] += a[i] * b[j];
        }
        __syncthreads();
    }
    // Epilogue: add bias, scatter into K/Q/V (split order is K,Q,V!)
#pragma unroll
    for (int i = 0; i < 8; i++) {
        int m = m0 + tr * 8 + i;
        int bb = m >> 11;        // / N_
        int n  = m & (N_ - 1);
#pragma unroll
        for (int j = 0; j < 8; j++) {
            int c  = n0 + tc * 8 + j;
            int hh = c / 192;
            int ff = c - hh * 192;
            float val = acc[i][j] + bias[c];
            size_t base = (((size_t)bb * H_ + hh) * N_ + n) * HD_;
            if (ff < 64)        g_k[base + ff]        = val;
            else if (ff < 128)  g_q[base + ff - 64]   = val;
            else                g_v[base + ff - 128]  = val;
        }
    }
}

// ---------------------------------------------------------------------------
// Kernel 2: causal flash attention (online softmax), fp32.
// Block = one (b,h, 64-row q-tile). K/V processed in 32-row tiles.
// Thread (rg=tid/8, cg=tid%8): S rows {rg, rg+32} x cols {4cg..4cg+3};
// O dims interleaved {4cg..4cg+3, 32+4cg..}. Smem pitches chosen conflict-free
// (65 == 1 mod 32; 33 == 1 mod 32).
// ---------------------------------------------------------------------------
__global__ __launch_bounds__(256) void attn_kernel()
{
    __shared__ float Qs[64][65];
    __shared__ float Ks[32][65];
    __shared__ float Vs[32][65];
    __shared__ float Ps[64][33];

    const int tid = threadIdx.x;
    const int qt  = blockIdx.x;     // 0..31 (64 rows each)
    const int bh  = blockIdx.y;     // 0..31
    const int rg  = tid >> 3;       // 0..31
    const int cg  = tid & 7;        // 0..7

    const float* Qg = g_q + ((size_t)bh * N_ + qt * 64) * HD_;
    const float* Kg = g_k + (size_t)bh * N_ * HD_;
    const float* Vg = g_v + (size_t)bh * N_ * HD_;

    // Load Q tile, pre-scaled by 1/sqrt(HD)=0.125
    for (int i = tid; i < 64 * 16; i += 256) {
        int rr = i >> 4, seg = (i & 15) * 4;
        float4 q4 = *(const float4*)(Qg + rr * HD_ + seg);
        Qs[rr][seg + 0] = q4.x * 0.125f;
        Qs[rr][seg + 1] = q4.y * 0.125f;
        Qs[rr][seg + 2] = q4.z * 0.125f;
        Qs[rr][seg + 3] = q4.w * 0.125f;
    }

    float O[2][8];
#pragma unroll
    for (int a = 0; a < 2; a++)
#pragma unroll
        for (int i = 0; i < 8; i++) O[a][i] = 0.f;
    float mrow[2] = {-1e30f, -1e30f};
    float lrow[2] = {0.f, 0.f};
    const int gq0 = qt * 64 + rg;
    const int gq1 = gq0 + 32;
    const int ktmax = 2 * qt + 1;   // causal: last useful 32-wide k-tile

    for (int kt = 0; kt <= ktmax; kt++) {
        __syncthreads();            // protect Ks/Vs (and first-iter Qs) reads
        for (int i = tid; i < 32 * 16; i += 256) {
            int rr = i >> 4, seg = (i & 15) * 4;
            float4 k4 = *(const float4*)(Kg + (size_t)(kt * 32 + rr) * HD_ + seg);
            Ks[rr][seg + 0] = k4.x; Ks[rr][seg + 1] = k4.y;
            Ks[rr][seg + 2] = k4.z; Ks[rr][seg + 3] = k4.w;
            float4 v4 = *(const float4*)(Vg + (size_t)(kt * 32 + rr) * HD_ + seg);
            Vs[rr][seg + 0] = v4.x; Vs[rr][seg + 1] = v4.y;
            Vs[rr][seg + 2] = v4.z; Vs[rr][seg + 3] = v4.w;
        }
        __syncthreads();

        // S = Q K^T (2 rows x 4 cols per thread)
        float s[2][4];
#pragma unroll
        for (int a = 0; a < 2; a++)
#pragma unroll
            for (int j = 0; j < 4; j++) s[a][j] = 0.f;
#pragma unroll 8
        for (int d = 0; d < 64; d++) {
            float q0 = Qs[rg][d];
            float q1 = Qs[rg + 32][d];
#pragma unroll
            for (int j = 0; j < 4; j++) {
                float kv = Ks[cg * 4 + j][d];
                s[0][j] += q0 * kv;
                s[1][j] += q1 * kv;
            }
        }
        // Causal mask (only last two tiles of this q-tile can mask)
        if (kt >= 2 * qt) {
#pragma unroll
            for (int j = 0; j < 4; j++) {
                int gk = kt * 32 + cg * 4 + j;
                if (gk > gq0) s[0][j] = -1e30f;
                if (gk > gq1) s[1][j] = -1e30f;
            }
        }
        // Online softmax (reduce across the 8 cg-lanes of each row)
#pragma unroll
        for (int a = 0; a < 2; a++) {
            float tmax = fmaxf(fmaxf(s[a][0], s[a][1]), fmaxf(s[a][2], s[a][3]));
            tmax = fmaxf(tmax, __shfl_xor_sync(0xffffffffu, tmax, 1));
            tmax = fmaxf(tmax, __shfl_xor_sync(0xffffffffu, tmax, 2));
            tmax = fmaxf(tmax, __shfl_xor_sync(0xffffffffu, tmax, 4));
            float mnew = fmaxf(mrow[a], tmax);
            float lsum = 0.f;
#pragma unroll
            for (int j = 0; j < 4; j++) {
                float p = __expf(s[a][j] - mnew);
                s[a][j] = p;
                lsum += p;
            }
            lsum += __shfl_xor_sync(0xffffffffu, lsum, 1);
            lsum += __shfl_xor_sync(0xffffffffu, lsum, 2);
            lsum += __shfl_xor_sync(0xffffffffu, lsum, 4);
            float alpha = __expf(mrow[a] - mnew);
            lrow[a] = lrow[a] * alpha + lsum;
            mrow[a] = mnew;
            int row = rg + a * 32;
#pragma unroll
            for (int j = 0; j < 4; j++) Ps[row][cg * 4 + j] = s[a][j];
#pragma unroll
            for (int i = 0; i < 8; i++) O[a][i] *= alpha;
        }
        __syncwarp();   // Ps row written & read within the same warp

        // O += P @ V
#pragma unroll 4
        for (int k = 0; k < 32; k++) {
            float p0 = Ps[rg][k];
            float p1 = Ps[rg + 32][k];
#pragma unroll
            for (int i = 0; i < 8; i++) {
                int d = (i >> 2) * 32 + cg * 4 + (i & 3);
                float vv = Vs[k][d];
                O[0][i] += p0 * vv;
                O[1][i] += p1 * vv;
            }
        }
    }

    // Finalize: O /= l, store to g_sa[b, n, h*64 + d]
    const int b = bh / H_;
    const int h = bh % H_;
#pragma unroll
    for (int a = 0; a < 2; a++) {
        int n = qt * 64 + rg + a * 32;
        float inv = 1.f / lrow[a];
        float* outp = g_sa + ((size_t)b * N_ + n) * E_ + h * HD_;
        float4 o0, o1;
        o0.x = O[a][0] * inv; o0.y = O[a][1] * inv;
        o0.z = O[a][2] * inv; o0.w = O[a][3] * inv;
        o1.x = O[a][4] * inv; o1.y = O[a][5] * inv;
        o1.z = O[a][6] * inv; o1.w = O[a][7] * inv;
        *(float4*)(outp + cg * 4)      = o0;
        *(float4*)(outp + 32 + cg * 4) = o1;
    }
}

// ---------------------------------------------------------------------------
// Kernel 3: output projection. out = g_sa @ Wout + bout
// Same 128x128x8 SGEMM structure.
// ---------------------------------------------------------------------------
__global__ __launch_bounds__(256) void out_gemm_kernel(
    const float* __restrict__ W, const float* __restrict__ bias,
    float* __restrict__ out)
{
    __shared__ float As[8][128];
    __shared__ float Bs[8][128];
    const int tid = threadIdx.x;
    const int m0 = blockIdx.y * 128;
    const int n0 = blockIdx.x * 128;
    const int tr = tid >> 4, tc = tid & 15;

    float acc[8][8];
#pragma unroll
    for (int i = 0; i < 8; i++)
#pragma unroll
        for (int j = 0; j < 8; j++) acc[i][j] = 0.f;

    const int aRow = tid >> 1;
    const int aSeg = (tid & 1) * 4;
    const int bRow = tid >> 5;
    const int bCol = (tid & 31) * 4;
    const float* Abase = g_sa + (size_t)(m0 + aRow) * E_ + aSeg;
    const float* Bbase = W + n0 + bCol;

    for (int k0 = 0; k0 < E_; k0 += 8) {
        float4 a4 = *(const float4*)(Abase + k0);
        As[aSeg + 0][aRow] = a4.x;
        As[aSeg + 1][aRow] = a4.y;
        As[aSeg + 2][aRow] = a4.z;
        As[aSeg + 3][aRow] = a4.w;
        float4 b4 = *(const float4*)(Bbase + (size_t)(k0 + bRow) * E_);
        *(float4*)(&Bs[bRow][bCol]) = b4;
        __syncthreads();
#pragma unroll
        for (int kk = 0; kk < 8; kk++) {
            float a[8], b[8];
            *(float4*)&a[0] = *(const float4*)&As[kk][tr * 8];
            *(float4*)&a[4] = *(const float4*)&As[kk][tr * 8 + 4];
            *(float4*)&b[0] = *(const float4*)&Bs[kk][tc * 8];
            *(float4*)&b[4] = *(const float4*)&Bs[kk][tc * 8 + 4];
#pragma unroll
            for (int i = 0; i < 8; i++)
#pragma unroll
                for (int j = 0; j < 8; j++) acc[i][j] += a[i] * b[j];
        }
        __syncthreads();
    }
#pragma unroll
    for (int i = 0; i < 8; i++) {
        int m = m0 + tr * 8 + i;
        float* op = out + (size_t)m * E_ + n0 + tc * 8;
        const float* bp = bias + n0 + tc * 8;
        float4 v0, v1;
        v0.x = acc[i][0] + bp[0]; v0.y = acc[i][1] + bp[1];
        v0.z = acc[i][2] + bp[2]; v0.w = acc[i][3] + bp[3];
        v1.x = acc[i][4] + bp[4]; v1.y = acc[i][5] + bp[5];
        v1.z = acc[i][6] + bp[6]; v1.w = acc[i][7] + bp[7];
        *(float4*)(op)     = v0;
        *(float4*)(op + 4) = v1;
    }
}

// ---------------------------------------------------------------------------
extern "C" void kernel_launch(void* const* d_in, const int* in_sizes, int n_in,
                              void* d_out, int out_size)
{
    const float* x    = (const float*)d_in[0];   // [B,N,E]
    const float* Wqkv = (const float*)d_in[1];   // [H,E,192]
    const float* bqkv = (const float*)d_in[2];   // [H,192]
    const float* Wout = (const float*)d_in[3];   // [E,E]
    const float* bout = (const float*)d_in[4];   // [E]
    float* out = (float*)d_out;                  // [B,N,E]

    dim3 g1(QKVC / 128, M_ / 128);   // 24 x 32
    qkv_gemm_kernel<<<g1, 256>>>(x, Wqkv, bqkv);

    dim3 g2(N_ / 64, B_ * H_);       // 32 x 32
    attn_kernel<<<g2, 256>>>();

    dim3 g3(E_ / 128, M_ / 128);     // 8 x 32
    out_gemm_kernel<<<g3, 256>>>(Wout, bout, out);
}

// round 3
// speedup vs baseline: 3.2376x; 3.2376x over previous
#include <cuda_runtime.h>
#include <cuda_bf16.h>
#include <cstdint>

#define B_   2
#define N_   2048
#define E_   1024
#define H_   16
#define HD_  64
#define M_   (B_*N_)        // 4096
#define QKVC (H_*3*HD_)     // 3072

typedef __nv_bfloat16 bf16;

// ---------------- scratch (static __device__, no allocs) ----------------
__device__ bf16 g_xh [M_*E_],      g_xl [M_*E_];
__device__ bf16 g_wqh[H_*E_*192],  g_wql[H_*E_*192];
__device__ bf16 g_woh[E_*E_],      g_wol[E_*E_];
__device__ bf16 g_qh [B_*H_*N_*HD_], g_ql[B_*H_*N_*HD_];
__device__ bf16 g_kh [B_*H_*N_*HD_], g_kl[B_*H_*N_*HD_];
__device__ bf16 g_vh [B_*H_*N_*HD_], g_vl[B_*H_*N_*HD_];
__device__ bf16 g_sah[M_*E_],      g_sal[M_*E_];

// ---------------- helpers ----------------
__device__ __forceinline__ uint32_t smem_u32(const void* p) {
    uint32_t a;
    asm("{ .reg .u64 t; cvta.to.shared.u64 t, %1; cvt.u32.u64 %0, t; }"
        : "=r"(a) : "l"(p));
    return a;
}
__device__ __forceinline__ void mma_bf16(float c[4], const uint32_t a[4],
                                         uint32_t b0, uint32_t b1) {
    asm volatile(
        "mma.sync.aligned.m16n8k16.row.col.f32.bf16.bf16.f32 "
        "{%0,%1,%2,%3}, {%4,%5,%6,%7}, {%8,%9}, {%0,%1,%2,%3};"
        : "+f"(c[0]), "+f"(c[1]), "+f"(c[2]), "+f"(c[3])
        : "r"(a[0]), "r"(a[1]), "r"(a[2]), "r"(a[3]), "r"(b0), "r"(b1));
}
__device__ __forceinline__ void ldm4(uint32_t r[4], uint32_t addr) {
    asm volatile("ldmatrix.sync.aligned.m8n8.x4.shared.b16 {%0,%1,%2,%3}, [%4];"
                 : "=r"(r[0]), "=r"(r[1]), "=r"(r[2]), "=r"(r[3]) : "r"(addr));
}
__device__ __forceinline__ void ldm4t(uint32_t r[4], uint32_t addr) {
    asm volatile("ldmatrix.sync.aligned.m8n8.x4.trans.shared.b16 {%0,%1,%2,%3}, [%4];"
                 : "=r"(r[0]), "=r"(r[1]), "=r"(r[2]), "=r"(r[3]) : "r"(addr));
}
__device__ __forceinline__ void split2(float v0, float v1, uint32_t& hp, uint32_t& lp) {
    __nv_bfloat16 h0 = __float2bfloat16_rn(v0);
    __nv_bfloat16 h1 = __float2bfloat16_rn(v1);
    __nv_bfloat16 l0 = __float2bfloat16_rn(v0 - __bfloat162float(h0));
    __nv_bfloat16 l1 = __float2bfloat16_rn(v1 - __bfloat162float(h1));
    hp = (uint32_t)__bfloat16_as_ushort(h0) | ((uint32_t)__bfloat16_as_ushort(h1) << 16);
    lp = (uint32_t)__bfloat16_as_ushort(l0) | ((uint32_t)__bfloat16_as_ushort(l1) << 16);
}

// ---------------- pre-pass: fp32 -> bf16 hi/lo planes ----------------
__global__ void split_kernel(const float* __restrict__ src, bf16* __restrict__ h,
                             bf16* __restrict__ l, int n4)
{
    int i = blockIdx.x * blockDim.x + threadIdx.x;
    int stride = gridDim.x * blockDim.x;
    for (; i < n4; i += stride) {
        float4 v = ((const float4*)src)[i];
        uint32_t h0, l0, h1, l1;
        split2(v.x, v.y, h0, l0);
        split2(v.z, v.w, h1, l1);
        ((uint2*)h)[i] = make_uint2(h0, h1);
        ((uint2*)l)[i] = make_uint2(l0, l1);
    }
}

// ---------------- kernel 1: QKV projection (HMMA, 3-term bf16) ----------------
// C[m, c] = sum_e X[m,e]*Wqkv[h,e,f] + bqkv[c], c=h*192+f; split K,Q,V -> bf16 hi/lo planes
__global__ __launch_bounds__(256) void qkv_mma(const float* __restrict__ bias)
{
    __shared__ __align__(16) uint8_t sm[37888];
    const uint32_t sb = smem_u32(sm);
    const uint32_t AH = sb, AL = sb + 10240, BH = sb + 20480, BL = sb + 29184;
    const int tid = threadIdx.x, lane = tid & 31, wid = tid >> 5;
    const int wm = wid >> 1, wn = wid & 1;
    const int m0 = blockIdx.y * 128, n0 = blockIdx.x * 128;
    const int g = lane >> 2, cq = (lane & 3) * 2;
    const int lrA = (lane & 7) + ((lane >> 3) & 1) * 8, lcA = ((lane >> 4) & 1) * 8;

    float acc[2][8][4];
#pragma unroll
    for (int t = 0; t < 2; t++)
#pragma unroll
        for (int nt = 0; nt < 8; nt++)
#pragma unroll
            for (int j = 0; j < 4; j++) acc[t][nt][j] = 0.f;

    uint4 pa[4], pb[4];
#pragma unroll
    for (int t = 0; t < 4; t++) {          // prefetch kc=0
        const bf16* s = (t < 2) ? g_xh : g_xl;
        int j = (t & 1) * 256 + tid, row = j >> 2, sg = (j & 3) * 8;
        pa[t] = ((const uint4*)s)[((size_t)(m0 + row) * E_ + sg) >> 3];
    }
#pragma unroll
    for (int t = 0; t < 4; t++) {
        const bf16* s = (t < 2) ? g_wqh : g_wql;
        int j = (t & 1) * 256 + tid, k = j >> 4, sg = (j & 15) * 8;
        int col = n0 + sg, hh = col / 192, ff = col - hh * 192;
        pb[t] = ((const uint4*)s)[((size_t)(hh * E_ + k) * 192 + ff) >> 3];
    }

    for (int kc = 0; kc < 32; kc++) {
#pragma unroll
        for (int t = 0; t < 4; t++) {
            int j = (t & 1) * 256 + tid, row = j >> 2, sg = (j & 3) * 8;
            *(uint4*)((t < 2 ? AH : AL) + row * 80 + sg * 2 - sb + (size_t)sm) = pa[t];
        }
#pragma unroll
        for (int t = 0; t < 4; t++) {
            int j = (t & 1) * 256 + tid, k = j >> 4, sg = (j & 15) * 8;
            *(uint4*)((t < 2 ? BH : BL) + k * 272 + sg * 2 - sb + (size_t)sm) = pb[t];
        }
        __syncthreads();
        if (kc < 31) {
            const int K0 = (kc + 1) * 32;
#pragma unroll
            for (int t = 0; t < 4; t++) {
                const bf16* s = (t < 2) ? g_xh : g_xl;
                int j = (t & 1) * 256 + tid, row = j >> 2, sg = (j & 3) * 8;
                pa[t] = ((const uint4*)s)[((size_t)(m0 + row) * E_ + K0 + sg) >> 3];
            }
#pragma unroll
            for (int t = 0; t < 4; t++) {
                const bf16* s = (t < 2) ? g_wqh : g_wql;
                int j = (t & 1) * 256 + tid, k = j >> 4, sg = (j & 15) * 8;
                int col = n0 + sg, hh = col / 192, ff = col - hh * 192;
                pb[t] = ((const uint4*)s)[((size_t)(hh * E_ + K0 + k) * 192 + ff) >> 3];
            }
        }
#pragma unroll
        for (int kk = 0; kk < 2; kk++) {
            uint32_t ah[2][4], al2[2][4], bh[4][4], bl[4][4];
#pragma unroll
            for (int t = 0; t < 2; t++) {
                uint32_t ao = (wm * 32 + t * 16 + lrA) * 80 + (kk * 16 + lcA) * 2;
                ldm4(ah[t],  AH + ao);
                ldm4(al2[t], AL + ao);
            }
#pragma unroll
            for (int np = 0; np < 4; np++) {
                uint32_t bo = (kk * 16 + lrA) * 272 + (wn * 64 + np * 16 + lcA) * 2;
                ldm4t(bh[np], BH + bo);
                ldm4t(bl[np], BL + bo);
            }
#pragma unroll
            for (int t = 0; t < 2; t++)
#pragma unroll
                for (int nt = 0; nt < 8; nt++)
                    mma_bf16(acc[t][nt], ah[t], bh[nt >> 1][(nt & 1) * 2], bh[nt >> 1][(nt & 1) * 2 + 1]);
#pragma unroll
            for (int t = 0; t < 2; t++)
#pragma unroll
                for (int nt = 0; nt < 8; nt++)
                    mma_bf16(acc[t][nt], ah[t], bl[nt >> 1][(nt & 1) * 2], bl[nt >> 1][(nt & 1) * 2 + 1]);
#pragma unroll
            for (int t = 0; t < 2; t++)
#pragma unroll
                for (int nt = 0; nt < 8; nt++)
                    mma_bf16(acc[t][nt], al2[t], bh[nt >> 1][(nt & 1) * 2], bh[nt >> 1][(nt & 1) * 2 + 1]);
        }
        __syncthreads();
    }

    // epilogue: +bias, split bf16, scatter to K/Q/V hi/lo planes (split order K,Q,V)
#pragma unroll
    for (int t = 0; t < 2; t++)
#pragma unroll
        for (int nt = 0; nt < 8; nt++) {
            int col = n0 + wn * 64 + nt * 8 + cq;
            float b0v = bias[col], b1v = bias[col + 1];
            int hh = col / 192, ff = col - hh * 192;
            int sel = ff >> 6, ffl = ff & 63;
            bf16 *ph = (sel == 0) ? g_kh : (sel == 1) ? g_qh : g_vh;
            bf16 *pl = (sel == 0) ? g_kl : (sel == 1) ? g_ql : g_vl;
#pragma unroll
            for (int rh = 0; rh < 2; rh++) {
                int m = m0 + wm * 32 + t * 16 + g + rh * 8;
                int bb = m >> 11, n = m & (N_ - 1);
                float v0 = acc[t][nt][rh * 2 + 0] + b0v;
                float v1 = acc[t][nt][rh * 2 + 1] + b1v;
                uint32_t hp, lp;
                split2(v0, v1, hp, lp);
                size_t idx = ((size_t)(bb * H_ + hh) * N_ + n) * HD_ + ffl;
                *(uint32_t*)(ph + idx) = hp;
                *(uint32_t*)(pl + idx) = lp;
            }
        }
}

// ---------------- kernel 2: causal flash attention (HMMA, 3-term bf16) ----------------
// block = (q-tile of 128 rows, b*h); 8 warps x 16 q-rows; 64-key tiles
__global__ __launch_bounds__(256) void attn_mma()
{
    __shared__ __align__(16) uint8_t sm[36864];
    const uint32_t sb = smem_u32(sm);
    const uint32_t KH = sb, KL = sb + 9216, VH = sb + 18432, VL = sb + 27648;
    const uint32_t QH = sb, QL = sb + 18432;
    const int tid = threadIdx.x, lane = tid & 31, w = tid >> 5;
    const int qt = blockIdx.x, bh = blockIdx.y;
    const int g = lane >> 2, cq = (lane & 3) * 2;
    const int lrA = (lane & 7) + ((lane >> 3) & 1) * 8, lcA = ((lane >> 4) & 1) * 8;
    const int lrB = (lane & 7) + ((lane >> 4) & 1) * 8, lcB = ((lane >> 3) & 1) * 8;

    // stage Q (128x64 hi/lo) into smem
#pragma unroll
    for (int t = 0; t < 8; t++) {
        const bf16* s = (t < 4) ? g_qh : g_ql;
        int j = (t & 3) * 256 + tid, row = j >> 3, sg = (j & 7) * 8;
        uint4 v = ((const uint4*)s)[((size_t)(bh * N_ + qt * 128 + row) * HD_ + sg) >> 3];
        *(uint4*)((size_t)sm + ((t < 4 ? QH : QL) - sb) + row * 144 + sg * 2) = v;
    }
    __syncthreads();
    uint32_t qh[4][4], ql[4][4];
#pragma unroll
    for (int kk = 0; kk < 4; kk++) {
        uint32_t qo = (w * 16 + lrA) * 144 + (kk * 16 + lcA) * 2;
        ldm4(qh[kk], QH + qo);
        ldm4(ql[kk], QL + qo);
    }

    float o[8][4];
#pragma unroll
    for (int nt = 0; nt < 8; nt++)
#pragma unroll
        for (int j = 0; j < 4; j++) o[nt][j] = 0.f;
    float mrow[2] = {-1e30f, -1e30f}, lrow[2] = {0.f, 0.f};
    const int qr0 = qt * 128 + w * 16 + g;
    const int wmaxk = qt * 128 + w * 16 + 15;
    const int ktmax = 2 * qt + 1;

    uint4 pk[8];
#pragma unroll
    for (int t = 0; t < 8; t++) {           // prefetch kt=0
        const bf16* s = (t < 2) ? g_kh : (t < 4) ? g_kl : (t < 6) ? g_vh : g_vl;
        int j = (t & 1) * 256 + tid, row = j >> 3, sg = (j & 7) * 8;
        pk[t] = ((const uint4*)s)[((size_t)(bh * N_ + row) * HD_ + sg) >> 3];
    }
    __syncthreads();

    for (int kt = 0; kt <= ktmax; kt++) {
#pragma unroll
        for (int t = 0; t < 8; t++) {
            int j = (t & 1) * 256 + tid, row = j >> 3, sg = (j & 7) * 8;
            uint32_t dst = (t < 2) ? KH : (t < 4) ? KL : (t < 6) ? VH : VL;
            *(uint4*)((size_t)sm + (dst - sb) + row * 144 + sg * 2) = pk[t];
        }
        __syncthreads();
        if (kt < ktmax) {
#pragma unroll
            for (int t = 0; t < 8; t++) {
                const bf16* s = (t < 2) ? g_kh : (t < 4) ? g_kl : (t < 6) ? g_vh : g_vl;
                int j = (t & 1) * 256 + tid, row = j >> 3, sg = (j & 7) * 8;
                pk[t] = ((const uint4*)s)[((size_t)(bh * N_ + (kt + 1) * 64 + row) * HD_ + sg) >> 3];
            }
        }
        if (kt * 64 <= wmaxk) {
            // S = Q K^T (3-term)
            float s_[8][4];
#pragma unroll
            for (int nt = 0; nt < 8; nt++)
#pragma unroll
                for (int j = 0; j < 4; j++) s_[nt][j] = 0.f;
#pragma unroll
            for (int kk = 0; kk < 4; kk++) {
                uint32_t kh_[4][4], kl_[4][4];
#pragma unroll
                for (int np = 0; np < 4; np++) {
                    uint32_t ko = (np * 16 + lrB) * 144 + (kk * 16 + lcB) * 2;
                    ldm4(kh_[np], KH + ko);
                    ldm4(kl_[np], KL + ko);
                }
#pragma unroll
                for (int nt = 0; nt < 8; nt++)
                    mma_bf16(s_[nt], qh[kk], kh_[nt >> 1][(nt & 1) * 2], kh_[nt >> 1][(nt & 1) * 2 + 1]);
#pragma unroll
                for (int nt = 0; nt < 8; nt++)
                    mma_bf16(s_[nt], qh[kk], kl_[nt >> 1][(nt & 1) * 2], kl_[nt >> 1][(nt & 1) * 2 + 1]);
#pragma unroll
                for (int nt = 0; nt < 8; nt++)
                    mma_bf16(s_[nt], ql[kk], kh_[nt >> 1][(nt & 1) * 2], kh_[nt >> 1][(nt & 1) * 2 + 1]);
            }
            // scale + causal mask
            const int kbase = kt * 64;
#pragma unroll
            for (int nt = 0; nt < 8; nt++)
#pragma unroll
                for (int j = 0; j < 4; j++) {
                    float sv = s_[nt][j] * 0.125f;
                    int colg = kbase + nt * 8 + cq + (j & 1);
                    int rowg = (j < 2) ? qr0 : qr0 + 8;
                    if (colg > rowg) sv = -1e30f;
                    s_[nt][j] = sv;
                }
            // online softmax (quad reduction over lane&3)
#pragma unroll
            for (int a = 0; a < 2; a++) {
                float tm = -1e30f;
#pragma unroll
                for (int nt = 0; nt < 8; nt++)
                    tm = fmaxf(tm, fmaxf(s_[nt][a * 2], s_[nt][a * 2 + 1]));
                tm = fmaxf(tm, __shfl_xor_sync(0xffffffffu, tm, 1));
                tm = fmaxf(tm, __shfl_xor_sync(0xffffffffu, tm, 2));
                float mn = fmaxf(mrow[a], tm);
                float alpha = __expf(mrow[a] - mn);
                float rs = 0.f;
#pragma unroll
                for (int nt = 0; nt < 8; nt++)
#pragma unroll
                    for (int jj = 0; jj < 2; jj++) {
                        float p = __expf(s_[nt][a * 2 + jj] - mn);
                        s_[nt][a * 2 + jj] = p;
                        rs += p;
                    }
                rs += __shfl_xor_sync(0xffffffffu, rs, 1);
                rs += __shfl_xor_sync(0xffffffffu, rs, 2);
                lrow[a] = lrow[a] * alpha + rs;
                mrow[a] = mn;
#pragma unroll
                for (int nt = 0; nt < 8; nt++) {
                    o[nt][a * 2]     *= alpha;
                    o[nt][a * 2 + 1] *= alpha;
                }
            }
            // O += P V (3-term); P a-frags come straight from s_ c-frags
#pragma unroll
            for (int kk = 0; kk < 4; kk++) {
                uint32_t pah[4], pal[4];
                split2(s_[2 * kk][0],     s_[2 * kk][1],     pah[0], pal[0]);
                split2(s_[2 * kk][2],     s_[2 * kk][3],     pah[1], pal[1]);
                split2(s_[2 * kk + 1][0], s_[2 * kk + 1][1], pah[2], pal[2]);
                split2(s_[2 * kk + 1][2], s_[2 * kk + 1][3], pah[3], pal[3]);
                uint32_t vh_[4][4], vl_[4][4];
#pragma unroll
                for (int np = 0; np < 4; np++) {
                    uint32_t vo = (kk * 16 + lrA) * 144 + (np * 16 + lcA) * 2;
                    ldm4t(vh_[np], VH + vo);
                    ldm4t(vl_[np], VL + vo);
                }
#pragma unroll
                for (int nt = 0; nt < 8; nt++)
                    mma_bf16(o[nt], pah, vh_[nt >> 1][(nt & 1) * 2], vh_[nt >> 1][(nt & 1) * 2 + 1]);
#pragma unroll
                for (int nt = 0; nt < 8; nt++)
                    mma_bf16(o[nt], pah, vl_[nt >> 1][(nt & 1) * 2], vl_[nt >> 1][(nt & 1) * 2 + 1]);
#pragma unroll
                for (int nt = 0; nt < 8; nt++)
                    mma_bf16(o[nt], pal, vh_[nt >> 1][(nt & 1) * 2], vh_[nt >> 1][(nt & 1) * 2 + 1]);
            }
        }
        __syncthreads();
    }

    // epilogue: O/l -> bf16 hi/lo planes of sa [B,N,E]
    const int bb = bh >> 4, hh = bh & 15;
    float inv[2] = {1.f / lrow[0], 1.f / lrow[1]};
#pragma unroll
    for (int nt = 0; nt < 8; nt++) {
        int d = hh * 64 + nt * 8 + cq;
#pragma unroll
        for (int a = 0; a < 2; a++) {
            int n = qt * 128 + w * 16 + g + a * 8;
            float v0 = o[nt][a * 2]     * inv[a];
            float v1 = o[nt][a * 2 + 1] * inv[a];
            uint32_t hp, lp;
            split2(v0, v1, hp, lp);
            size_t idx = (size_t)(bb * N_ + n) * E_ + d;
            *(uint32_t*)(g_sah + idx) = hp;
            *(uint32_t*)(g_sal + idx) = lp;
        }
    }
}

// ---------------- kernel 3: output projection (HMMA, 3-term bf16) ----------------
__global__ __launch_bounds__(256) void out_mma(const float* __restrict__ bias,
                                               float* __restrict__ out)
{
    __shared__ __align__(16) uint8_t sm[37888];
    const uint32_t sb = smem_u32(sm);
    const uint32_t AH = sb, AL = sb + 10240, BH = sb + 20480, BL = sb + 29184;
    const int tid = threadIdx.x, lane = tid & 31, wid = tid >> 5;
    const int wm = wid >> 1, wn = wid & 1;
    const int m0 = blockIdx.y * 128, n0 = blockIdx.x * 128;
    const int g = lane >> 2, cq = (lane & 3) * 2;
    const int lrA = (lane & 7) + ((lane >> 3) & 1) * 8, lcA = ((lane >> 4) & 1) * 8;

    float acc[2][8][4];
#pragma unroll
    for (int t = 0; t < 2; t++)
#pragma unroll
        for (int nt = 0; nt < 8; nt++)
#pragma unroll
            for (int j = 0; j < 4; j++) acc[t][nt][j] = 0.f;

    uint4 pa[4], pb[4];
#pragma unroll
    for (int t = 0; t < 4; t++) {
        const bf16* s = (t < 2) ? g_sah : g_sal;
        int j = (t & 1) * 256 + tid, row = j >> 2, sg = (j & 3) * 8;
        pa[t] = ((const uint4*)s)[((size_t)(m0 + row) * E_ + sg) >> 3];
    }
#pragma unroll
    for (int t = 0; t < 4; t++) {
        const bf16* s = (t < 2) ? g_woh : g_wol;
        int j = (t & 1) * 256 + tid, k = j >> 4, sg = (j & 15) * 8;
        pb[t] = ((const uint4*)s)[((size_t)k * E_ + n0 + sg) >> 3];
    }

    for (int kc = 0; kc < 32; kc++) {
#pragma unroll
        for (int t = 0; t < 4; t++) {
            int j = (t & 1) * 256 + tid, row = j >> 2, sg = (j & 3) * 8;
            *(uint4*)((size_t)sm + ((t < 2 ? AH : AL) - sb) + row * 80 + sg * 2) = pa[t];
        }
#pragma unroll
        for (int t = 0; t < 4; t++) {
            int j = (t & 1) * 256 + tid, k = j >> 4, sg = (j & 15) * 8;
            *(uint4*)((size_t)sm + ((t < 2 ? BH : BL) - sb) + k * 272 + sg * 2) = pb[t];
        }
        __syncthreads();
        if (kc < 31) {
            const int K0 = (kc + 1) * 32;
#pragma unroll
            for (int t = 0; t < 4; t++) {
                const bf16* s = (t < 2) ? g_sah : g_sal;
                int j = (t & 1) * 256 + tid, row = j >> 2, sg = (j & 3) * 8;
                pa[t] = ((const uint4*)s)[((size_t)(m0 + row) * E_ + K0 + sg) >> 3];
            }
#pragma unroll
            for (int t = 0; t < 4; t++) {
                const bf16* s = (t < 2) ? g_woh : g_wol;
                int j = (t & 1) * 256 + tid, k = j >> 4, sg = (j & 15) * 8;
                pb[t] = ((const uint4*)s)[((size_t)(K0 + k) * E_ + n0 + sg) >> 3];
            }
        }
#pragma unroll
        for (int kk = 0; kk < 2; kk++) {
            uint32_t ah[2][4], al2[2][4], bh[4][4], bl[4][4];
#pragma unroll
            for (int t = 0; t < 2; t++) {
                uint32_t ao = (wm * 32 + t * 16 + lrA) * 80 + (kk * 16 + lcA) * 2;
                ldm4(ah[t],  AH + ao);
                ldm4(al2[t], AL + ao);
            }
#pragma unroll
            for (int np = 0; np < 4; np++) {
                uint32_t bo = (kk * 16 + lrA) * 272 + (wn * 64 + np * 16 + lcA) * 2;
                ldm4t(bh[np], BH + bo);
                ldm4t(bl[np], BL + bo);
            }
#pragma unroll
            for (int t = 0; t < 2; t++)
#pragma unroll
                for (int nt = 0; nt < 8; nt++)
                    mma_bf16(acc[t][nt], ah[t], bh[nt >> 1][(nt & 1) * 2], bh[nt >> 1][(nt & 1) * 2 + 1]);
#pragma unroll
            for (int t = 0; t < 2; t++)
#pragma unroll
                for (int nt = 0; nt < 8; nt++)
                    mma_bf16(acc[t][nt], ah[t], bl[nt >> 1][(nt & 1) * 2], bl[nt >> 1][(nt & 1) * 2 + 1]);
#pragma unroll
            for (int t = 0; t < 2; t++)
#pragma unroll
                for (int nt = 0; nt < 8; nt++)
                    mma_bf16(acc[t][nt], al2[t], bh[nt >> 1][(nt & 1) * 2], bh[nt >> 1][(nt & 1) * 2 + 1]);
        }
        __syncthreads();
    }

#pragma unroll
    for (int t = 0; t < 2; t++)
#pragma unroll
        for (int nt = 0; nt < 8; nt++) {
            int col = n0 + wn * 64 + nt * 8 + cq;
            float b0v = bias[col], b1v = bias[col + 1];
#pragma unroll
            for (int rh = 0; rh < 2; rh++) {
                int m = m0 + wm * 32 + t * 16 + g + rh * 8;
                float2 v;
                v.x = acc[t][nt][rh * 2 + 0] + b0v;
                v.y = acc[t][nt][rh * 2 + 1] + b1v;
                *(float2*)(out + (size_t)m * E_ + col) = v;
            }
        }
}

// ---------------------------------------------------------------------------
extern "C" void kernel_launch(void* const* d_in, const int* in_sizes, int n_in,
                              void* d_out, int out_size)
{
    const float* x    = (const float*)d_in[0];   // [B,N,E]
    const float* Wqkv = (const float*)d_in[1];   // [H,E,192]
    const float* bqkv = (const float*)d_in[2];   // [H,192]
    const float* Wout = (const float*)d_in[3];   // [E,E]
    const float* bout = (const float*)d_in[4];   // [E]
    float* out = (float*)d_out;                  // [B,N,E]

    bf16 *xh, *xl, *wqh, *wql, *woh, *wol;
    cudaGetSymbolAddress((void**)&xh,  g_xh);
    cudaGetSymbolAddress((void**)&xl,  g_xl);
    cudaGetSymbolAddress((void**)&wqh, g_wqh);
    cudaGetSymbolAddress((void**)&wql, g_wql);
    cudaGetSymbolAddress((void**)&woh, g_woh);
    cudaGetSymbolAddress((void**)&wol, g_wol);

    split_kernel<<<1024, 256>>>(x,    xh,  xl,  (M_ * E_) / 4);
    split_kernel<<<1024, 256>>>(Wqkv, wqh, wql, (H_ * E_ * 192) / 4);
    split_kernel<<<1024, 256>>>(Wout, woh, wol, (E_ * E_) / 4);

    dim3 g1(QKVC / 128, M_ / 128);   // 24 x 32
    qkv_mma<<<g1, 256>>>(bqkv);

    dim3 g2(N_ / 128, B_ * H_);      // 16 x 32
    attn_mma<<<g2, 256>>>();

    dim3 g3(E_ / 128, M_ / 128);     // 8 x 32
    out_mma<<<g3, 256>>>(bout, out);
}

// round 4
// speedup vs baseline: 3.4464x; 1.0645x over previous
#include <cuda_runtime.h>
#include <cuda_bf16.h>
#include <cstdint>

#define B_   2
#define N_   2048
#define E_   1024
#define H_   16
#define HD_  64
#define M_   (B_*N_)        // 4096
#define QKVC (H_*3*HD_)     // 3072

typedef __nv_bfloat16 bf16;

// ---------------- scratch (static __device__, no allocs) ----------------
__device__ bf16 g_xh [M_*E_],      g_xl [M_*E_];
__device__ bf16 g_wqh[H_*E_*192],  g_wql[H_*E_*192];
__device__ bf16 g_woh[E_*E_],      g_wol[E_*E_];
__device__ bf16 g_qh [B_*H_*N_*HD_], g_ql[B_*H_*N_*HD_];
__device__ bf16 g_kh [B_*H_*N_*HD_], g_kl[B_*H_*N_*HD_];
__device__ bf16 g_vh [B_*H_*N_*HD_], g_vl[B_*H_*N_*HD_];
__device__ bf16 g_sah[M_*E_],      g_sal[M_*E_];

// ---------------- helpers ----------------
__device__ __forceinline__ uint32_t smem_u32(const void* p) {
    uint32_t a;
    asm("{ .reg .u64 t; cvta.to.shared.u64 t, %1; cvt.u32.u64 %0, t; }"
        : "=r"(a) : "l"(p));
    return a;
}
__device__ __forceinline__ void mma_bf16(float c[4], const uint32_t a[4],
                                         uint32_t b0, uint32_t b1) {
    asm volatile(
        "mma.sync.aligned.m16n8k16.row.col.f32.bf16.bf16.f32 "
        "{%0,%1,%2,%3}, {%4,%5,%6,%7}, {%8,%9}, {%0,%1,%2,%3};"
        : "+f"(c[0]), "+f"(c[1]), "+f"(c[2]), "+f"(c[3])
        : "r"(a[0]), "r"(a[1]), "r"(a[2]), "r"(a[3]), "r"(b0), "r"(b1));
}
__device__ __forceinline__ void ldm4(uint32_t r[4], uint32_t addr) {
    asm volatile("ldmatrix.sync.aligned.m8n8.x4.shared.b16 {%0,%1,%2,%3}, [%4];"
                 : "=r"(r[0]), "=r"(r[1]), "=r"(r[2]), "=r"(r[3]) : "r"(addr));
}
__device__ __forceinline__ void ldm4t(uint32_t r[4], uint32_t addr) {
    asm volatile("ldmatrix.sync.aligned.m8n8.x4.trans.shared.b16 {%0,%1,%2,%3}, [%4];"
                 : "=r"(r[0]), "=r"(r[1]), "=r"(r[2]), "=r"(r[3]) : "r"(addr));
}
__device__ __forceinline__ void split2(float v0, float v1, uint32_t& hp, uint32_t& lp) {
    __nv_bfloat16 h0 = __float2bfloat16_rn(v0);
    __nv_bfloat16 h1 = __float2bfloat16_rn(v1);
    __nv_bfloat16 l0 = __float2bfloat16_rn(v0 - __bfloat162float(h0));
    __nv_bfloat16 l1 = __float2bfloat16_rn(v1 - __bfloat162float(h1));
    hp = (uint32_t)__bfloat16_as_ushort(h0) | ((uint32_t)__bfloat16_as_ushort(h1) << 16);
    lp = (uint32_t)__bfloat16_as_ushort(l0) | ((uint32_t)__bfloat16_as_ushort(l1) << 16);
}
#define CP16(d, s)  asm volatile("cp.async.cg.shared.global [%0], [%1], 16;" :: "r"(d), "l"(s))
#define CP_COMMIT() asm volatile("cp.async.commit_group;" ::: "memory")
#define CP_WAIT0()  asm volatile("cp.async.wait_group 0;" ::: "memory")

// ---------------- pre-pass: fp32 -> bf16 hi/lo planes ----------------
__global__ void split_kernel(const float* __restrict__ src, bf16* __restrict__ h,
                             bf16* __restrict__ l, int n4)
{
    int i = blockIdx.x * blockDim.x + threadIdx.x;
    int stride = gridDim.x * blockDim.x;
    for (; i < n4; i += stride) {
        float4 v = ((const float4*)src)[i];
        uint32_t h0, l0, h1, l1;
        split2(v.x, v.y, h0, l0);
        split2(v.z, v.w, h1, l1);
        ((uint2*)h)[i] = make_uint2(h0, h1);
        ((uint2*)l)[i] = make_uint2(l0, l1);
    }
}

// GEMM smem geometry (per buffer, double buffered)
// AH @0 (pitch 80, 128 rows), AL @10240, BH @20480 (pitch 272, 32 rows), BL @29184
#define GBUF 37888
#define GEMM_SMEM (2*GBUF)

// ---------------- kernel 1: QKV projection (HMMA, 3-term bf16, cp.async pipeline) ----
__global__ __launch_bounds__(256) void qkv_mma(const float* __restrict__ bias)
{
    extern __shared__ __align__(16) uint8_t dsm[];
    const uint32_t sb = smem_u32(dsm);
    const int tid = threadIdx.x, lane = tid & 31, wid = tid >> 5;
    const int wm = wid >> 1, wn = wid & 1;
    const int m0 = blockIdx.y * 128, n0 = blockIdx.x * 128;
    const int g = lane >> 2, cq = (lane & 3) * 2;
    const int lrA = (lane & 7) + ((lane >> 3) & 1) * 8, lcA = ((lane >> 4) & 1) * 8;

    // per-thread cp.async descriptors
    const bf16* srcA[4]; uint32_t dstA[4];
    const bf16* srcB[4]; uint32_t dstB[4];
#pragma unroll
    for (int t = 0; t < 4; t++) {
        int j = (t & 1) * 256 + tid, row = j >> 2, sg = (j & 3) * 8;
        srcA[t] = ((t < 2) ? g_xh : g_xl) + (size_t)(m0 + row) * E_ + sg;
        dstA[t] = ((t < 2) ? 0u : 10240u) + row * 80 + sg * 2;
    }
#pragma unroll
    for (int t = 0; t < 4; t++) {
        int j = (t & 1) * 256 + tid, k = j >> 4, sg = (j & 15) * 8;
        int col = n0 + sg, hh = col / 192, ff = col - hh * 192;
        srcB[t] = ((t < 2) ? g_wqh : g_wql) + (size_t)(hh * E_ + k) * 192 + ff;
        dstB[t] = ((t < 2) ? 20480u : 29184u) + k * 272 + sg * 2;
    }

    float acc[2][8][4];
#pragma unroll
    for (int t = 0; t < 2; t++)
#pragma unroll
        for (int nt = 0; nt < 8; nt++)
#pragma unroll
            for (int j = 0; j < 4; j++) acc[t][nt][j] = 0.f;

    // prologue: chunk 0 -> buf 0
#pragma unroll
    for (int t = 0; t < 4; t++) CP16(sb + dstA[t], srcA[t]);
#pragma unroll
    for (int t = 0; t < 4; t++) CP16(sb + dstB[t], srcB[t]);
    CP_COMMIT();

    for (int kc = 0; kc < 32; kc++) {
        const uint32_t base = sb + (uint32_t)(kc & 1) * GBUF;
        CP_WAIT0();
        __syncthreads();
        if (kc < 31) {
            const uint32_t nb = sb + (uint32_t)((kc + 1) & 1) * GBUF;
#pragma unroll
            for (int t = 0; t < 4; t++) { srcA[t] += 32;       CP16(nb + dstA[t], srcA[t]); }
#pragma unroll
            for (int t = 0; t < 4; t++) { srcB[t] += 32 * 192; CP16(nb + dstB[t], srcB[t]); }
            CP_COMMIT();
        }
        const uint32_t AH = base, AL = base + 10240, BH = base + 20480, BL = base + 29184;
#pragma unroll
        for (int kk = 0; kk < 2; kk++) {
            uint32_t ah[2][4], al2[2][4], bh[4][4], bl[4][4];
#pragma unroll
            for (int t = 0; t < 2; t++) {
                uint32_t ao = (wm * 32 + t * 16 + lrA) * 80 + (kk * 16 + lcA) * 2;
                ldm4(ah[t],  AH + ao);
                ldm4(al2[t], AL + ao);
            }
#pragma unroll
            for (int np = 0; np < 4; np++) {
                uint32_t bo = (kk * 16 + lrA) * 272 + (wn * 64 + np * 16 + lcA) * 2;
                ldm4t(bh[np], BH + bo);
                ldm4t(bl[np], BL + bo);
            }
#pragma unroll
            for (int t = 0; t < 2; t++)
#pragma unroll
                for (int nt = 0; nt < 8; nt++)
                    mma_bf16(acc[t][nt], ah[t], bh[nt >> 1][(nt & 1) * 2], bh[nt >> 1][(nt & 1) * 2 + 1]);
#pragma unroll
            for (int t = 0; t < 2; t++)
#pragma unroll
                for (int nt = 0; nt < 8; nt++)
                    mma_bf16(acc[t][nt], ah[t], bl[nt >> 1][(nt & 1) * 2], bl[nt >> 1][(nt & 1) * 2 + 1]);
#pragma unroll
            for (int t = 0; t < 2; t++)
#pragma unroll
                for (int nt = 0; nt < 8; nt++)
                    mma_bf16(acc[t][nt], al2[t], bh[nt >> 1][(nt & 1) * 2], bh[nt >> 1][(nt & 1) * 2 + 1]);
        }
    }

    // epilogue: +bias, split bf16, scatter to K/Q/V hi/lo planes (split order K,Q,V)
#pragma unroll
    for (int t = 0; t < 2; t++)
#pragma unroll
        for (int nt = 0; nt < 8; nt++) {
            int col = n0 + wn * 64 + nt * 8 + cq;
            float b0v = bias[col], b1v = bias[col + 1];
            int hh = col / 192, ff = col - hh * 192;
            int sel = ff >> 6, ffl = ff & 63;
            bf16 *ph = (sel == 0) ? g_kh : (sel == 1) ? g_qh : g_vh;
            bf16 *pl = (sel == 0) ? g_kl : (sel == 1) ? g_ql : g_vl;
#pragma unroll
            for (int rh = 0; rh < 2; rh++) {
                int m = m0 + wm * 32 + t * 16 + g + rh * 8;
                int bb = m >> 11, n = m & (N_ - 1);
                float v0 = acc[t][nt][rh * 2 + 0] + b0v;
                float v1 = acc[t][nt][rh * 2 + 1] + b1v;
                uint32_t hp, lp;
                split2(v0, v1, hp, lp);
                size_t idx = ((size_t)(bb * H_ + hh) * N_ + n) * HD_ + ffl;
                *(uint32_t*)(ph + idx) = hp;
                *(uint32_t*)(pl + idx) = lp;
            }
        }
}

// ---------------- kernel 2: causal flash attention (HMMA, 3-term, cp.async) --------
// KV buffer stride 36864: KH@0, KL@9216, VH@18432, VL@27648 (pitch 144, 64 rows)
// Q staging: QH@73728, QL@92160 (pitch 144, 128 rows). Total 110592 B.
#define ABUF 36864
#define ATTN_SMEM (2*ABUF + 2*18432)
__global__ __launch_bounds__(256) void attn_mma()
{
    extern __shared__ __align__(16) uint8_t dsm[];
    const uint32_t sb = smem_u32(dsm);
    const int tid = threadIdx.x, lane = tid & 31, w = tid >> 5;
    const int qt = blockIdx.x, bhd = blockIdx.y;
    const int g = lane >> 2, cq = (lane & 3) * 2;
    const int lrA = (lane & 7) + ((lane >> 3) & 1) * 8, lcA = ((lane >> 4) & 1) * 8;
    const int lrB = (lane & 7) + ((lane >> 4) & 1) * 8, lcB = ((lane >> 3) & 1) * 8;
    const uint32_t QH = sb + 2 * ABUF, QL = QH + 18432;

    // cp.async descriptors for KV tiles
    const bf16* srcKV[8]; uint32_t dstKV[8];
#pragma unroll
    for (int t = 0; t < 8; t++) {
        const bf16* s = (t < 2) ? g_kh : (t < 4) ? g_kl : (t < 6) ? g_vh : g_vl;
        int j = (t & 1) * 256 + tid, row = j >> 3, sg = (j & 7) * 8;
        srcKV[t] = s + (size_t)(bhd * N_ + row) * HD_ + sg;
        dstKV[t] = ((t < 2) ? 0u : (t < 4) ? 9216u : (t < 6) ? 18432u : 27648u)
                 + row * 144 + sg * 2;
    }
    // prologue: kv tile 0 -> buf 0 (flies while we stage Q)
#pragma unroll
    for (int t = 0; t < 8; t++) CP16(sb + dstKV[t], srcKV[t]);
    CP_COMMIT();

    // stage Q (128x64 hi/lo)
#pragma unroll
    for (int t = 0; t < 8; t++) {
        const bf16* s = (t < 4) ? g_qh : g_ql;
        int j = (t & 3) * 256 + tid, row = j >> 3, sg = (j & 7) * 8;
        uint4 v = ((const uint4*)s)[((size_t)(bhd * N_ + qt * 128 + row) * HD_ + sg) >> 3];
        *(uint4*)((size_t)dsm + ((t < 4 ? QH : QL) - sb) + row * 144 + sg * 2) = v;
    }
    __syncthreads();
    uint32_t qh[4][4], ql[4][4];
#pragma unroll
    for (int kk = 0; kk < 4; kk++) {
        uint32_t qo = (w * 16 + lrA) * 144 + (kk * 16 + lcA) * 2;
        ldm4(qh[kk], QH + qo);
        ldm4(ql[kk], QL + qo);
    }

    float o[8][4];
#pragma unroll
    for (int nt = 0; nt < 8; nt++)
#pragma unroll
        for (int j = 0; j < 4; j++) o[nt][j] = 0.f;
    float mrow[2] = {-1e30f, -1e30f}, lrow[2] = {0.f, 0.f};
    const int qr0 = qt * 128 + w * 16 + g;
    const int wmaxk = qt * 128 + w * 16 + 15;
    const int ktmax = 2 * qt + 1;

    for (int kt = 0; kt <= ktmax; kt++) {
        const uint32_t base = sb + (uint32_t)(kt & 1) * ABUF;
        CP_WAIT0();
        __syncthreads();
        if (kt < ktmax) {
            const uint32_t nb = sb + (uint32_t)((kt + 1) & 1) * ABUF;
#pragma unroll
            for (int t = 0; t < 8; t++) { srcKV[t] += 64 * HD_; CP16(nb + dstKV[t], srcKV[t]); }
            CP_COMMIT();
        }
        if (kt * 64 <= wmaxk) {
            const uint32_t KH = base, KL = base + 9216, VH = base + 18432, VL = base + 27648;
            // S = Q K^T (3-term)
            float s_[8][4];
#pragma unroll
            for (int nt = 0; nt < 8; nt++)
#pragma unroll
                for (int j = 0; j < 4; j++) s_[nt][j] = 0.f;
#pragma unroll
            for (int kk = 0; kk < 4; kk++) {
                uint32_t kh_[4][4], kl_[4][4];
#pragma unroll
                for (int np = 0; np < 4; np++) {
                    uint32_t ko = (np * 16 + lrB) * 144 + (kk * 16 + lcB) * 2;
                    ldm4(kh_[np], KH + ko);
                    ldm4(kl_[np], KL + ko);
                }
#pragma unroll
                for (int nt = 0; nt < 8; nt++)
                    mma_bf16(s_[nt], qh[kk], kh_[nt >> 1][(nt & 1) * 2], kh_[nt >> 1][(nt & 1) * 2 + 1]);
#pragma unroll
                for (int nt = 0; nt < 8; nt++)
                    mma_bf16(s_[nt], qh[kk], kl_[nt >> 1][(nt & 1) * 2], kl_[nt >> 1][(nt & 1) * 2 + 1]);
#pragma unroll
                for (int nt = 0; nt < 8; nt++)
                    mma_bf16(s_[nt], ql[kk], kh_[nt >> 1][(nt & 1) * 2], kh_[nt >> 1][(nt & 1) * 2 + 1]);
            }
            // scale + causal mask
            const int kbase = kt * 64;
#pragma unroll
            for (int nt = 0; nt < 8; nt++)
#pragma unroll
                for (int j = 0; j < 4; j++) {
                    float sv = s_[nt][j] * 0.125f;
                    int colg = kbase + nt * 8 + cq + (j & 1);
                    int rowg = (j < 2) ? qr0 : qr0 + 8;
                    if (colg > rowg) sv = -1e30f;
                    s_[nt][j] = sv;
                }
            // online softmax (quad reduction over lane&3)
#pragma unroll
            for (int a = 0; a < 2; a++) {
                float tm = -1e30f;
#pragma unroll
                for (int nt = 0; nt < 8; nt++)
                    tm = fmaxf(tm, fmaxf(s_[nt][a * 2], s_[nt][a * 2 + 1]));
                tm = fmaxf(tm, __shfl_xor_sync(0xffffffffu, tm, 1));
                tm = fmaxf(tm, __shfl_xor_sync(0xffffffffu, tm, 2));
                float mn = fmaxf(mrow[a], tm);
                float alpha = __expf(mrow[a] - mn);
                float rs = 0.f;
#pragma unroll
                for (int nt = 0; nt < 8; nt++)
#pragma unroll
                    for (int jj = 0; jj < 2; jj++) {
                        float p = __expf(s_[nt][a * 2 + jj] - mn);
                        s_[nt][a * 2 + jj] = p;
                        rs += p;
                    }
                rs += __shfl_xor_sync(0xffffffffu, rs, 1);
                rs += __shfl_xor_sync(0xffffffffu, rs, 2);
                lrow[a] = lrow[a] * alpha + rs;
                mrow[a] = mn;
#pragma unroll
                for (int nt = 0; nt < 8; nt++) {
                    o[nt][a * 2]     *= alpha;
                    o[nt][a * 2 + 1] *= alpha;
                }
            }
            // O += P V (3-term); P a-frags straight from s_ c-frags
#pragma unroll
            for (int kk = 0; kk < 4; kk++) {
                uint32_t pah[4], pal[4];
                split2(s_[2 * kk][0],     s_[2 * kk][1],     pah[0], pal[0]);
                split2(s_[2 * kk][2],     s_[2 * kk][3],     pah[1], pal[1]);
                split2(s_[2 * kk + 1][0], s_[2 * kk + 1][1], pah[2], pal[2]);
                split2(s_[2 * kk + 1][2], s_[2 * kk + 1][3], pah[3], pal[3]);
                uint32_t vh_[4][4], vl_[4][4];
#pragma unroll
                for (int np = 0; np < 4; np++) {
                    uint32_t vo = (kk * 16 + lrA) * 144 + (np * 16 + lcA) * 2;
                    ldm4t(vh_[np], VH + vo);
                    ldm4t(vl_[np], VL + vo);
                }
#pragma unroll
                for (int nt = 0; nt < 8; nt++)
                    mma_bf16(o[nt], pah, vh_[nt >> 1][(nt & 1) * 2], vh_[nt >> 1][(nt & 1) * 2 + 1]);
#pragma unroll
                for (int nt = 0; nt < 8; nt++)
                    mma_bf16(o[nt], pah, vl_[nt >> 1][(nt & 1) * 2], vl_[nt >> 1][(nt & 1) * 2 + 1]);
#pragma unroll
                for (int nt = 0; nt < 8; nt++)
                    mma_bf16(o[nt], pal, vh_[nt >> 1][(nt & 1) * 2], vh_[nt >> 1][(nt & 1) * 2 + 1]);
            }
        }
    }

    // epilogue: O/l -> bf16 hi/lo planes of sa [B,N,E]
    const int bb = bhd >> 4, hh = bhd & 15;
    float inv[2] = {1.f / lrow[0], 1.f / lrow[1]};
#pragma unroll
    for (int nt = 0; nt < 8; nt++) {
        int d = hh * 64 + nt * 8 + cq;
#pragma unroll
        for (int a = 0; a < 2; a++) {
            int n = qt * 128 + w * 16 + g + a * 8;
            float v0 = o[nt][a * 2]     * inv[a];
            float v1 = o[nt][a * 2 + 1] * inv[a];
            uint32_t hp, lp;
            split2(v0, v1, hp, lp);
            size_t idx = (size_t)(bb * N_ + n) * E_ + d;
            *(uint32_t*)(g_sah + idx) = hp;
            *(uint32_t*)(g_sal + idx) = lp;
        }
    }
}

// ---------------- kernel 3: output projection (HMMA, 3-term, cp.async) --------------
__global__ __launch_bounds__(256) void out_mma(const float* __restrict__ bias,
                                               float* __restrict__ out)
{
    extern __shared__ __align__(16) uint8_t dsm[];
    const uint32_t sb = smem_u32(dsm);
    const int tid = threadIdx.x, lane = tid & 31, wid = tid >> 5;
    const int wm = wid >> 1, wn = wid & 1;
    const int m0 = blockIdx.y * 128, n0 = blockIdx.x * 128;
    const int g = lane >> 2, cq = (lane & 3) * 2;
    const int lrA = (lane & 7) + ((lane >> 3) & 1) * 8, lcA = ((lane >> 4) & 1) * 8;

    const bf16* srcA[4]; uint32_t dstA[4];
    const bf16* srcB[4]; uint32_t dstB[4];
#pragma unroll
    for (int t = 0; t < 4; t++) {
        int j = (t & 1) * 256 + tid, row = j >> 2, sg = (j & 3) * 8;
        srcA[t] = ((t < 2) ? g_sah : g_sal) + (size_t)(m0 + row) * E_ + sg;
        dstA[t] = ((t < 2) ? 0u : 10240u) + row * 80 + sg * 2;
    }
#pragma unroll
    for (int t = 0; t < 4; t++) {
        int j = (t & 1) * 256 + tid, k = j >> 4, sg = (j & 15) * 8;
        srcB[t] = ((t < 2) ? g_woh : g_wol) + (size_t)k * E_ + n0 + sg;
        dstB[t] = ((t < 2) ? 20480u : 29184u) + k * 272 + sg * 2;
    }

    float acc[2][8][4];
#pragma unroll
    for (int t = 0; t < 2; t++)
#pragma unroll
        for (int nt = 0; nt < 8; nt++)
#pragma unroll
            for (int j = 0; j < 4; j++) acc[t][nt][j] = 0.f;

#pragma unroll
    for (int t = 0; t < 4; t++) CP16(sb + dstA[t], srcA[t]);
#pragma unroll
    for (int t = 0; t < 4; t++) CP16(sb + dstB[t], srcB[t]);
    CP_COMMIT();

    for (int kc = 0; kc < 32; kc++) {
        const uint32_t base = sb + (uint32_t)(kc & 1) * GBUF;
        CP_WAIT0();
        __syncthreads();
        if (kc < 31) {
            const uint32_t nb = sb + (uint32_t)((kc + 1) & 1) * GBUF;
#pragma unroll
            for (int t = 0; t < 4; t++) { srcA[t] += 32;      CP16(nb + dstA[t], srcA[t]); }
#pragma unroll
            for (int t = 0; t < 4; t++) { srcB[t] += 32 * E_; CP16(nb + dstB[t], srcB[t]); }
            CP_COMMIT();
        }
        const uint32_t AH = base, AL = base + 10240, BH = base + 20480, BL = base + 29184;
#pragma unroll
        for (int kk = 0; kk < 2; kk++) {
            uint32_t ah[2][4], al2[2][4], bh[4][4], bl[4][4];
#pragma unroll
            for (int t = 0; t < 2; t++) {
                uint32_t ao = (wm * 32 + t * 16 + lrA) * 80 + (kk * 16 + lcA) * 2;
                ldm4(ah[t],  AH + ao);
                ldm4(al2[t], AL + ao);
            }
#pragma unroll
            for (int np = 0; np < 4; np++) {
                uint32_t bo = (kk * 16 + lrA) * 272 + (wn * 64 + np * 16 + lcA) * 2;
                ldm4t(bh[np], BH + bo);
                ldm4t(bl[np], BL + bo);
            }
#pragma unroll
            for (int t = 0; t < 2; t++)
#pragma unroll
                for (int nt = 0; nt < 8; nt++)
                    mma_bf16(acc[t][nt], ah[t], bh[nt >> 1][(nt & 1) * 2], bh[nt >> 1][(nt & 1) * 2 + 1]);
#pragma unroll
            for (int t = 0; t < 2; t++)
#pragma unroll
                for (int nt = 0; nt < 8; nt++)
                    mma_bf16(acc[t][nt], ah[t], bl[nt >> 1][(nt & 1) * 2], bl[nt >> 1][(nt & 1) * 2 + 1]);
#pragma unroll
            for (int t = 0; t < 2; t++)
#pragma unroll
                for (int nt = 0; nt < 8; nt++)
                    mma_bf16(acc[t][nt], al2[t], bh[nt >> 1][(nt & 1) * 2], bh[nt >> 1][(nt & 1) * 2 + 1]);
        }
    }

#pragma unroll
    for (int t = 0; t < 2; t++)
#pragma unroll
        for (int nt = 0; nt < 8; nt++) {
            int col = n0 + wn * 64 + nt * 8 + cq;
            float b0v = bias[col], b1v = bias[col + 1];
#pragma unroll
            for (int rh = 0; rh < 2; rh++) {
                int m = m0 + wm * 32 + t * 16 + g + rh * 8;
                float2 v;
                v.x = acc[t][nt][rh * 2 + 0] + b0v;
                v.y = acc[t][nt][rh * 2 + 1] + b1v;
                *(float2*)(out + (size_t)m * E_ + col) = v;
            }
        }
}

// ---------------------------------------------------------------------------
extern "C" void kernel_launch(void* const* d_in, const int* in_sizes, int n_in,
                              void* d_out, int out_size)
{
    const float* x    = (const float*)d_in[0];   // [B,N,E]
    const float* Wqkv = (const float*)d_in[1];   // [H,E,192]
    const float* bqkv = (const float*)d_in[2];   // [H,192]
    const float* Wout = (const float*)d_in[3];   // [E,E]
    const float* bout = (const float*)d_in[4];   // [E]
    float* out = (float*)d_out;                  // [B,N,E]

    static int configured = 0;
    if (!configured) {
        cudaFuncSetAttribute(qkv_mma,  cudaFuncAttributeMaxDynamicSharedMemorySize, GEMM_SMEM);
        cudaFuncSetAttribute(out_mma,  cudaFuncAttributeMaxDynamicSharedMemorySize, GEMM_SMEM);
        cudaFuncSetAttribute(attn_mma, cudaFuncAttributeMaxDynamicSharedMemorySize, ATTN_SMEM);
        configured = 1;
    }

    bf16 *xh, *xl, *wqh, *wql, *woh, *wol;
    cudaGetSymbolAddress((void**)&xh,  g_xh);
    cudaGetSymbolAddress((void**)&xl,  g_xl);
    cudaGetSymbolAddress((void**)&wqh, g_wqh);
    cudaGetSymbolAddress((void**)&wql, g_wql);
    cudaGetSymbolAddress((void**)&woh, g_woh);
    cudaGetSymbolAddress((void**)&wol, g_wol);

    split_kernel<<<1024, 256>>>(x,    xh,  xl,  (M_ * E_) / 4);
    split_kernel<<<1024, 256>>>(Wqkv, wqh, wql, (H_ * E_ * 192) / 4);
    split_kernel<<<1024, 256>>>(Wout, woh, wol, (E_ * E_) / 4);

    dim3 g1(QKVC / 128, M_ / 128);   // 24 x 32
    qkv_mma<<<g1, 256, GEMM_SMEM>>>(bqkv);

    dim3 g2(N_ / 128, B_ * H_);      // 16 x 32
    attn_mma<<<g2, 256, ATTN_SMEM>>>();

    dim3 g3(E_ / 128, M_ / 128);     // 8 x 32
    out_mma<<<g3, 256, GEMM_SMEM>>>(bout, out);
}

// round 5
// speedup vs baseline: 3.5630x; 1.0338x over previous
#include <cuda_runtime.h>
#include <cuda_bf16.h>
#include <cstdint>

#define B_   2
#define N_   2048
#define E_   1024
#define H_   16
#define HD_  64
#define M_   (B_*N_)        // 4096
#define QKVC (H_*3*HD_)     // 3072

typedef __nv_bfloat16 bf16;

// ---------------- scratch (static __device__, no allocs) ----------------
__device__ bf16 g_xh [M_*E_],      g_xl [M_*E_];
__device__ bf16 g_wqh[H_*E_*192],  g_wql[H_*E_*192];
__device__ bf16 g_woh[E_*E_],      g_wol[E_*E_];
__device__ bf16 g_qh [B_*H_*N_*HD_], g_ql[B_*H_*N_*HD_];
__device__ bf16 g_kh [B_*H_*N_*HD_], g_kl[B_*H_*N_*HD_];
__device__ bf16 g_vh [B_*H_*N_*HD_], g_vl[B_*H_*N_*HD_];
__device__ bf16 g_sah[M_*E_],      g_sal[M_*E_];

// ---------------- helpers ----------------
__device__ __forceinline__ uint32_t smem_u32(const void* p) {
    uint32_t a;
    asm("{ .reg .u64 t; cvta.to.shared.u64 t, %1; cvt.u32.u64 %0, t; }"
        : "=r"(a) : "l"(p));
    return a;
}
__device__ __forceinline__ void mma_bf16(float c[4], const uint32_t a[4],
                                         uint32_t b0, uint32_t b1) {
    asm volatile(
        "mma.sync.aligned.m16n8k16.row.col.f32.bf16.bf16.f32 "
        "{%0,%1,%2,%3}, {%4,%5,%6,%7}, {%8,%9}, {%0,%1,%2,%3};"
        : "+f"(c[0]), "+f"(c[1]), "+f"(c[2]), "+f"(c[3])
        : "r"(a[0]), "r"(a[1]), "r"(a[2]), "r"(a[3]), "r"(b0), "r"(b1));
}
__device__ __forceinline__ void ldm4(uint32_t r[4], uint32_t addr) {
    asm volatile("ldmatrix.sync.aligned.m8n8.x4.shared.b16 {%0,%1,%2,%3}, [%4];"
                 : "=r"(r[0]), "=r"(r[1]), "=r"(r[2]), "=r"(r[3]) : "r"(addr));
}
__device__ __forceinline__ void ldm4t(uint32_t r[4], uint32_t addr) {
    asm volatile("ldmatrix.sync.aligned.m8n8.x4.trans.shared.b16 {%0,%1,%2,%3}, [%4];"
                 : "=r"(r[0]), "=r"(r[1]), "=r"(r[2]), "=r"(r[3]) : "r"(addr));
}
__device__ __forceinline__ void split2(float v0, float v1, uint32_t& hp, uint32_t& lp) {
    __nv_bfloat16 h0 = __float2bfloat16_rn(v0);
    __nv_bfloat16 h1 = __float2bfloat16_rn(v1);
    __nv_bfloat16 l0 = __float2bfloat16_rn(v0 - __bfloat162float(h0));
    __nv_bfloat16 l1 = __float2bfloat16_rn(v1 - __bfloat162float(h1));
    hp = (uint32_t)__bfloat16_as_ushort(h0) | ((uint32_t)__bfloat16_as_ushort(h1) << 16);
    lp = (uint32_t)__bfloat16_as_ushort(l0) | ((uint32_t)__bfloat16_as_ushort(l1) << 16);
}
#define CP16(d, s)  asm volatile("cp.async.cg.shared.global [%0], [%1], 16;" :: "r"(d), "l"(s))
#define CP_COMMIT() asm volatile("cp.async.commit_group;" ::: "memory")
#define CP_WAIT0()  asm volatile("cp.async.wait_group 0;" ::: "memory")

// ---------------- pre-pass: fp32 -> bf16 hi/lo planes ----------------
__global__ void split_kernel(const float* __restrict__ src, bf16* __restrict__ h,
                             bf16* __restrict__ l, int n4)
{
    int i = blockIdx.x * blockDim.x + threadIdx.x;
    int stride = gridDim.x * blockDim.x;
    for (; i < n4; i += stride) {
        float4 v = ((const float4*)src)[i];
        uint32_t h0, l0, h1, l1;
        split2(v.x, v.y, h0, l0);
        split2(v.z, v.w, h1, l1);
        ((uint2*)h)[i] = make_uint2(h0, h1);
        ((uint2*)l)[i] = make_uint2(l0, l1);
    }
}

// GEMM smem geometry (per buffer, double buffered)
// AH @0 (pitch 80, 128 rows), AL @10240, BH @20480 (pitch 272, 32 rows), BL @29184
#define GBUF 37888
#define GEMM_SMEM (2*GBUF)

// Shared inner compute: one K-chunk's 2 kk sub-steps with half-resident B frags.
#define GEMM_KCHUNK_BODY(AH, AL, BH, BL)                                              \
    _Pragma("unroll")                                                                 \
    for (int kk = 0; kk < 2; kk++) {                                                  \
        uint32_t ah[2][4], al2[2][4];                                                 \
        _Pragma("unroll")                                                             \
        for (int t = 0; t < 2; t++) {                                                 \
            uint32_t ao = (wm * 32 + t * 16 + lrA) * 80 + (kk * 16 + lcA) * 2;        \
            ldm4(ah[t],  (AH) + ao);                                                  \
            ldm4(al2[t], (AL) + ao);                                                  \
        }                                                                             \
        _Pragma("unroll")                                                             \
        for (int half = 0; half < 2; half++) {                                        \
            uint32_t bh2[2][4], bl2[2][4];                                            \
            _Pragma("unroll")                                                         \
            for (int p = 0; p < 2; p++) {                                             \
                int np = half * 2 + p;                                                \
                uint32_t bo = (kk * 16 + lrA) * 272 + (wn * 64 + np * 16 + lcA) * 2;  \
                ldm4t(bh2[p], (BH) + bo);                                             \
                ldm4t(bl2[p], (BL) + bo);                                             \
            }                                                                         \
            _Pragma("unroll")                                                         \
            for (int t = 0; t < 2; t++)                                               \
            _Pragma("unroll")                                                         \
            for (int p = 0; p < 2; p++)                                               \
            _Pragma("unroll")                                                         \
            for (int j = 0; j < 2; j++)                                               \
                mma_bf16(acc[t][(half * 2 + p) * 2 + j], ah[t],                       \
                         bh2[p][j * 2], bh2[p][j * 2 + 1]);                           \
            _Pragma("unroll")                                                         \
            for (int t = 0; t < 2; t++)                                               \
            _Pragma("unroll")                                                         \
            for (int p = 0; p < 2; p++)                                               \
            _Pragma("unroll")                                                         \
            for (int j = 0; j < 2; j++)                                               \
                mma_bf16(acc[t][(half * 2 + p) * 2 + j], ah[t],                       \
                         bl2[p][j * 2], bl2[p][j * 2 + 1]);                           \
            _Pragma("unroll")                                                         \
            for (int t = 0; t < 2; t++)                                               \
            _Pragma("unroll")                                                         \
            for (int p = 0; p < 2; p++)                                               \
            _Pragma("unroll")                                                         \
            for (int j = 0; j < 2; j++)                                               \
                mma_bf16(acc[t][(half * 2 + p) * 2 + j], al2[t],                      \
                         bh2[p][j * 2], bh2[p][j * 2 + 1]);                           \
        }                                                                             \
    }

// ---------------- kernel 1: QKV projection ----------------
__global__ __launch_bounds__(256, 2) void qkv_mma(const float* __restrict__ bias)
{
    extern __shared__ __align__(16) uint8_t dsm[];
    const uint32_t sb = smem_u32(dsm);
    const int tid = threadIdx.x, lane = tid & 31, wid = tid >> 5;
    const int wm = wid >> 1, wn = wid & 1;
    const int m0 = blockIdx.y * 128, n0 = blockIdx.x * 128;
    const int g = lane >> 2, cq = (lane & 3) * 2;
    const int lrA = (lane & 7) + ((lane >> 3) & 1) * 8, lcA = ((lane >> 4) & 1) * 8;

    const bf16* srcA[4]; uint32_t dstA[4];
    const bf16* srcB[4]; uint32_t dstB[4];
#pragma unroll
    for (int t = 0; t < 4; t++) {
        int j = (t & 1) * 256 + tid, row = j >> 2, sg = (j & 3) * 8;
        srcA[t] = ((t < 2) ? g_xh : g_xl) + (size_t)(m0 + row) * E_ + sg;
        dstA[t] = ((t < 2) ? 0u : 10240u) + row * 80 + sg * 2;
    }
#pragma unroll
    for (int t = 0; t < 4; t++) {
        int j = (t & 1) * 256 + tid, k = j >> 4, sg = (j & 15) * 8;
        int col = n0 + sg, hh = col / 192, ff = col - hh * 192;
        srcB[t] = ((t < 2) ? g_wqh : g_wql) + (size_t)(hh * E_ + k) * 192 + ff;
        dstB[t] = ((t < 2) ? 20480u : 29184u) + k * 272 + sg * 2;
    }

    float acc[2][8][4];
#pragma unroll
    for (int t = 0; t < 2; t++)
#pragma unroll
        for (int nt = 0; nt < 8; nt++)
#pragma unroll
            for (int j = 0; j < 4; j++) acc[t][nt][j] = 0.f;

#pragma unroll
    for (int t = 0; t < 4; t++) CP16(sb + dstA[t], srcA[t]);
#pragma unroll
    for (int t = 0; t < 4; t++) CP16(sb + dstB[t], srcB[t]);
    CP_COMMIT();

    for (int kc = 0; kc < 32; kc++) {
        const uint32_t base = sb + (uint32_t)(kc & 1) * GBUF;
        CP_WAIT0();
        __syncthreads();
        if (kc < 31) {
            const uint32_t nb = sb + (uint32_t)((kc + 1) & 1) * GBUF;
#pragma unroll
            for (int t = 0; t < 4; t++) { srcA[t] += 32;       CP16(nb + dstA[t], srcA[t]); }
#pragma unroll
            for (int t = 0; t < 4; t++) { srcB[t] += 32 * 192; CP16(nb + dstB[t], srcB[t]); }
            CP_COMMIT();
        }
        GEMM_KCHUNK_BODY(base, base + 10240, base + 20480, base + 29184)
    }

    // epilogue: +bias, split bf16, scatter to K/Q/V hi/lo planes (split order K,Q,V)
#pragma unroll
    for (int t = 0; t < 2; t++)
#pragma unroll
        for (int nt = 0; nt < 8; nt++) {
            int col = n0 + wn * 64 + nt * 8 + cq;
            float b0v = bias[col], b1v = bias[col + 1];
            int hh = col / 192, ff = col - hh * 192;
            int sel = ff >> 6, ffl = ff & 63;
            bf16 *ph = (sel == 0) ? g_kh : (sel == 1) ? g_qh : g_vh;
            bf16 *pl = (sel == 0) ? g_kl : (sel == 1) ? g_ql : g_vl;
#pragma unroll
            for (int rh = 0; rh < 2; rh++) {
                int m = m0 + wm * 32 + t * 16 + g + rh * 8;
                int bb = m >> 11, n = m & (N_ - 1);
                float v0 = acc[t][nt][rh * 2 + 0] + b0v;
                float v1 = acc[t][nt][rh * 2 + 1] + b1v;
                uint32_t hp, lp;
                split2(v0, v1, hp, lp);
                size_t idx = ((size_t)(bb * H_ + hh) * N_ + n) * HD_ + ffl;
                *(uint32_t*)(ph + idx) = hp;
                *(uint32_t*)(pl + idx) = lp;
            }
        }
}

// ---------------- kernel 2: causal flash attention --------
// KV buffer stride 36864: KH@0, KL@9216, VH@18432, VL@27648 (pitch 144, 64 rows)
// Q staging: QH@73728, QL@92160 (pitch 144, 128 rows). Total 110592 B.
#define ABUF 36864
#define ATTN_SMEM (2*ABUF + 2*18432)
__global__ __launch_bounds__(256, 2) void attn_mma()
{
    extern __shared__ __align__(16) uint8_t dsm[];
    const uint32_t sb = smem_u32(dsm);
    const int tid = threadIdx.x, lane = tid & 31, w = tid >> 5;
    const int qt = blockIdx.x, bhd = blockIdx.y;
    const int g = lane >> 2, cq = (lane & 3) * 2;
    const int lrA = (lane & 7) + ((lane >> 3) & 1) * 8, lcA = ((lane >> 4) & 1) * 8;
    const int lrB = (lane & 7) + ((lane >> 4) & 1) * 8, lcB = ((lane >> 3) & 1) * 8;
    const uint32_t QH = sb + 2 * ABUF, QL = QH + 18432;

    const bf16* srcKV[8]; uint32_t dstKV[8];
#pragma unroll
    for (int t = 0; t < 8; t++) {
        const bf16* s = (t < 2) ? g_kh : (t < 4) ? g_kl : (t < 6) ? g_vh : g_vl;
        int j = (t & 1) * 256 + tid, row = j >> 3, sg = (j & 7) * 8;
        srcKV[t] = s + (size_t)(bhd * N_ + row) * HD_ + sg;
        dstKV[t] = ((t < 2) ? 0u : (t < 4) ? 9216u : (t < 6) ? 18432u : 27648u)
                 + row * 144 + sg * 2;
    }
#pragma unroll
    for (int t = 0; t < 8; t++) CP16(sb + dstKV[t], srcKV[t]);
    CP_COMMIT();

    // stage Q (128x64 hi/lo) — stays in smem; frags loaded on demand per kk
#pragma unroll
    for (int t = 0; t < 8; t++) {
        const bf16* s = (t < 4) ? g_qh : g_ql;
        int j = (t & 3) * 256 + tid, row = j >> 3, sg = (j & 7) * 8;
        uint4 v = ((const uint4*)s)[((size_t)(bhd * N_ + qt * 128 + row) * HD_ + sg) >> 3];
        *(uint4*)((size_t)dsm + ((t < 4 ? QH : QL) - sb) + row * 144 + sg * 2) = v;
    }

    float o[8][4];
#pragma unroll
    for (int nt = 0; nt < 8; nt++)
#pragma unroll
        for (int j = 0; j < 4; j++) o[nt][j] = 0.f;
    float mrow[2] = {-1e30f, -1e30f}, lrow[2] = {0.f, 0.f};
    const int qr0 = qt * 128 + w * 16 + g;
    const int wmaxk = qt * 128 + w * 16 + 15;
    const int ktmax = 2 * qt + 1;

    for (int kt = 0; kt <= ktmax; kt++) {
        const uint32_t base = sb + (uint32_t)(kt & 1) * ABUF;
        CP_WAIT0();
        __syncthreads();
        if (kt < ktmax) {
            const uint32_t nb = sb + (uint32_t)((kt + 1) & 1) * ABUF;
#pragma unroll
            for (int t = 0; t < 8; t++) { srcKV[t] += 64 * HD_; CP16(nb + dstKV[t], srcKV[t]); }
            CP_COMMIT();
        }
        if (kt * 64 <= wmaxk) {
            const uint32_t KH = base, KL = base + 9216, VH = base + 18432, VL = base + 27648;
            // S = Q K^T (3-term), K frags half-resident, Q frags on demand
            float s_[8][4];
#pragma unroll
            for (int nt = 0; nt < 8; nt++)
#pragma unroll
                for (int j = 0; j < 4; j++) s_[nt][j] = 0.f;
#pragma unroll
            for (int kk = 0; kk < 4; kk++) {
                uint32_t qhf[4], qlf[4];
                uint32_t qo = (w * 16 + lrA) * 144 + (kk * 16 + lcA) * 2;
                ldm4(qhf, QH + qo);
                ldm4(qlf, QL + qo);
#pragma unroll
                for (int half = 0; half < 2; half++) {
                    uint32_t kh2[2][4], kl2[2][4];
#pragma unroll
                    for (int p = 0; p < 2; p++) {
                        int np = half * 2 + p;
                        uint32_t ko = (np * 16 + lrB) * 144 + (kk * 16 + lcB) * 2;
                        ldm4(kh2[p], KH + ko);
                        ldm4(kl2[p], KL + ko);
                    }
#pragma unroll
                    for (int p = 0; p < 2; p++)
#pragma unroll
                        for (int j = 0; j < 2; j++)
                            mma_bf16(s_[(half * 2 + p) * 2 + j], qhf,
                                     kh2[p][j * 2], kh2[p][j * 2 + 1]);
#pragma unroll
                    for (int p = 0; p < 2; p++)
#pragma unroll
                        for (int j = 0; j < 2; j++)
                            mma_bf16(s_[(half * 2 + p) * 2 + j], qhf,
                                     kl2[p][j * 2], kl2[p][j * 2 + 1]);
#pragma unroll
                    for (int p = 0; p < 2; p++)
#pragma unroll
                        for (int j = 0; j < 2; j++)
                            mma_bf16(s_[(half * 2 + p) * 2 + j], qlf,
                                     kh2[p][j * 2], kh2[p][j * 2 + 1]);
                }
            }
            // scale + causal mask
            const int kbase = kt * 64;
#pragma unroll
            for (int nt = 0; nt < 8; nt++)
#pragma unroll
                for (int j = 0; j < 4; j++) {
                    float sv = s_[nt][j] * 0.125f;
                    int colg = kbase + nt * 8 + cq + (j & 1);
                    int rowg = (j < 2) ? qr0 : qr0 + 8;
                    if (colg > rowg) sv = -1e30f;
                    s_[nt][j] = sv;
                }
            // online softmax (quad reduction over lane&3)
#pragma unroll
            for (int a = 0; a < 2; a++) {
                float tm = -1e30f;
#pragma unroll
                for (int nt = 0; nt < 8; nt++)
                    tm = fmaxf(tm, fmaxf(s_[nt][a * 2], s_[nt][a * 2 + 1]));
                tm = fmaxf(tm, __shfl_xor_sync(0xffffffffu, tm, 1));
                tm = fmaxf(tm, __shfl_xor_sync(0xffffffffu, tm, 2));
                float mn = fmaxf(mrow[a], tm);
                float alpha = __expf(mrow[a] - mn);
                float rs = 0.f;
#pragma unroll
                for (int nt = 0; nt < 8; nt++)
#pragma unroll
                    for (int jj = 0; jj < 2; jj++) {
                        float p = __expf(s_[nt][a * 2 + jj] - mn);
                        s_[nt][a * 2 + jj] = p;
                        rs += p;
                    }
                rs += __shfl_xor_sync(0xffffffffu, rs, 1);
                rs += __shfl_xor_sync(0xffffffffu, rs, 2);
                lrow[a] = lrow[a] * alpha + rs;
                mrow[a] = mn;
#pragma unroll
                for (int nt = 0; nt < 8; nt++) {
                    o[nt][a * 2]     *= alpha;
                    o[nt][a * 2 + 1] *= alpha;
                }
            }
            // O += P V (3-term); V frags half-resident
#pragma unroll
            for (int kk = 0; kk < 4; kk++) {
                uint32_t pah[4], pal[4];
                split2(s_[2 * kk][0],     s_[2 * kk][1],     pah[0], pal[0]);
                split2(s_[2 * kk][2],     s_[2 * kk][3],     pah[1], pal[1]);
                split2(s_[2 * kk + 1][0], s_[2 * kk + 1][1], pah[2], pal[2]);
                split2(s_[2 * kk + 1][2], s_[2 * kk + 1][3], pah[3], pal[3]);
#pragma unroll
                for (int half = 0; half < 2; half++) {
                    uint32_t vh2[2][4], vl2[2][4];
#pragma unroll
                    for (int p = 0; p < 2; p++) {
                        int np = half * 2 + p;
                        uint32_t vo = (kk * 16 + lrA) * 144 + (np * 16 + lcA) * 2;
                        ldm4t(vh2[p], VH + vo);
                        ldm4t(vl2[p], VL + vo);
                    }
#pragma unroll
                    for (int p = 0; p < 2; p++)
#pragma unroll
                        for (int j = 0; j < 2; j++)
                            mma_bf16(o[(half * 2 + p) * 2 + j], pah,
                                     vh2[p][j * 2], vh2[p][j * 2 + 1]);
#pragma unroll
                    for (int p = 0; p < 2; p++)
#pragma unroll
                        for (int j = 0; j < 2; j++)
                            mma_bf16(o[(half * 2 + p) * 2 + j], pah,
                                     vl2[p][j * 2], vl2[p][j * 2 + 1]);
#pragma unroll
                    for (int p = 0; p < 2; p++)
#pragma unroll
                        for (int j = 0; j < 2; j++)
                            mma_bf16(o[(half * 2 + p) * 2 + j], pal,
                                     vh2[p][j * 2], vh2[p][j * 2 + 1]);
                }
            }
        }
    }

    // epilogue: O/l -> bf16 hi/lo planes of sa [B,N,E]
    const int bb = bhd >> 4, hh = bhd & 15;
    float inv[2] = {1.f / lrow[0], 1.f / lrow[1]};
#pragma unroll
    for (int nt = 0; nt < 8; nt++) {
        int d = hh * 64 + nt * 8 + cq;
#pragma unroll
        for (int a = 0; a < 2; a++) {
            int n = qt * 128 + w * 16 + g + a * 8;
            float v0 = o[nt][a * 2]     * inv[a];
            float v1 = o[nt][a * 2 + 1] * inv[a];
            uint32_t hp, lp;
            split2(v0, v1, hp, lp);
            size_t idx = (size_t)(bb * N_ + n) * E_ + d;
            *(uint32_t*)(g_sah + idx) = hp;
            *(uint32_t*)(g_sal + idx) = lp;
        }
    }
}

// ---------------- kernel 3: output projection --------------
__global__ __launch_bounds__(256, 2) void out_mma(const float* __restrict__ bias,
                                                  float* __restrict__ out)
{
    extern __shared__ __align__(16) uint8_t dsm[];
    const uint32_t sb = smem_u32(dsm);
    const int tid = threadIdx.x, lane = tid & 31, wid = tid >> 5;
    const int wm = wid >> 1, wn = wid & 1;
    const int m0 = blockIdx.y * 128, n0 = blockIdx.x * 128;
    const int g = lane >> 2, cq = (lane & 3) * 2;
    const int lrA = (lane & 7) + ((lane >> 3) & 1) * 8, lcA = ((lane >> 4) & 1) * 8;

    const bf16* srcA[4]; uint32_t dstA[4];
    const bf16* srcB[4]; uint32_t dstB[4];
#pragma unroll
    for (int t = 0; t < 4; t++) {
        int j = (t & 1) * 256 + tid, row = j >> 2, sg = (j & 3) * 8;
        srcA[t] = ((t < 2) ? g_sah : g_sal) + (size_t)(m0 + row) * E_ + sg;
        dstA[t] = ((t < 2) ? 0u : 10240u) + row * 80 + sg * 2;
    }
#pragma unroll
    for (int t = 0; t < 4; t++) {
        int j = (t & 1) * 256 + tid, k = j >> 4, sg = (j & 15) * 8;
        srcB[t] = ((t < 2) ? g_woh : g_wol) + (size_t)k * E_ + n0 + sg;
        dstB[t] = ((t < 2) ? 20480u : 29184u) + k * 272 + sg * 2;
    }

    float acc[2][8][4];
#pragma unroll
    for (int t = 0; t < 2; t++)
#pragma unroll
        for (int nt = 0; nt < 8; nt++)
#pragma unroll
            for (int j = 0; j < 4; j++) acc[t][nt][j] = 0.f;

#pragma unroll
    for (int t = 0; t < 4; t++) CP16(sb + dstA[t], srcA[t]);
#pragma unroll
    for (int t = 0; t < 4; t++) CP16(sb + dstB[t], srcB[t]);
    CP_COMMIT();

    for (int kc = 0; kc < 32; kc++) {
        const uint32_t base = sb + (uint32_t)(kc & 1) * GBUF;
        CP_WAIT0();
        __syncthreads();
        if (kc < 31) {
            const uint32_t nb = sb + (uint32_t)((kc + 1) & 1) * GBUF;
#pragma unroll
            for (int t = 0; t < 4; t++) { srcA[t] += 32;      CP16(nb + dstA[t], srcA[t]); }
#pragma unroll
            for (int t = 0; t < 4; t++) { srcB[t] += 32 * E_; CP16(nb + dstB[t], srcB[t]); }
            CP_COMMIT();
        }
        GEMM_KCHUNK_BODY(base, base + 10240, base + 20480, base + 29184)
    }

#pragma unroll
    for (int t = 0; t < 2; t++)
#pragma unroll
        for (int nt = 0; nt < 8; nt++) {
            int col = n0 + wn * 64 + nt * 8 + cq;
            float b0v = bias[col], b1v = bias[col + 1];
#pragma unroll
            for (int rh = 0; rh < 2; rh++) {
                int m = m0 + wm * 32 + t * 16 + g + rh * 8;
                float2 v;
                v.x = acc[t][nt][rh * 2 + 0] + b0v;
                v.y = acc[t][nt][rh * 2 + 1] + b1v;
                *(float2*)(out + (size_t)m * E_ + col) = v;
            }
        }
}

// ---------------------------------------------------------------------------
extern "C" void kernel_launch(void* const* d_in, const int* in_sizes, int n_in,
                              void* d_out, int out_size)
{
    const float* x    = (const float*)d_in[0];   // [B,N,E]
    const float* Wqkv = (const float*)d_in[1];   // [H,E,192]
    const float* bqkv = (const float*)d_in[2];   // [H,192]
    const float* Wout = (const float*)d_in[3];   // [E,E]
    const float* bout = (const float*)d_in[4];   // [E]
    float* out = (float*)d_out;                  // [B,N,E]

    static int configured = 0;
    if (!configured) {
        cudaFuncSetAttribute(qkv_mma,  cudaFuncAttributeMaxDynamicSharedMemorySize, GEMM_SMEM);
        cudaFuncSetAttribute(out_mma,  cudaFuncAttributeMaxDynamicSharedMemorySize, GEMM_SMEM);
        cudaFuncSetAttribute(attn_mma, cudaFuncAttributeMaxDynamicSharedMemorySize, ATTN_SMEM);
        configured = 1;
    }

    bf16 *xh, *xl, *wqh, *wql, *woh, *wol;
    cudaGetSymbolAddress((void**)&xh,  g_xh);
    cudaGetSymbolAddress((void**)&xl,  g_xl);
    cudaGetSymbolAddress((void**)&wqh, g_wqh);
    cudaGetSymbolAddress((void**)&wql, g_wql);
    cudaGetSymbolAddress((void**)&woh, g_woh);
    cudaGetSymbolAddress((void**)&wol, g_wol);

    split_kernel<<<1024, 256>>>(x,    xh,  xl,  (M_ * E_) / 4);
    split_kernel<<<1024, 256>>>(Wqkv, wqh, wql, (H_ * E_ * 192) / 4);
    split_kernel<<<1024, 256>>>(Wout, woh, wol, (E_ * E_) / 4);

    dim3 g1(QKVC / 128, M_ / 128);   // 24 x 32
    qkv_mma<<<g1, 256, GEMM_SMEM>>>(bqkv);

    dim3 g2(N_ / 128, B_ * H_);      // 16 x 32
    attn_mma<<<g2, 256, ATTN_SMEM>>>();

    dim3 g3(E_ / 128, M_ / 128);     // 8 x 32
    out_mma<<<g3, 256, GEMM_SMEM>>>(bout, out);
}

// round 6
// speedup vs baseline: 8.5088x; 2.3881x over previous
#include <cuda_runtime.h>
#include <cuda_fp16.h>
#include <cstdint>

#define B_   2
#define N_   2048
#define E_   1024
#define H_   16
#define HD_  64
#define M_   (B_*N_)        // 4096
#define QKVC (H_*3*HD_)     // 3072

typedef __half fp16;

// ---------------- scratch (static __device__, no allocs) ----------------
__device__ fp16 g_x16 [M_*E_];
__device__ fp16 g_wq16[H_*E_*192];
__device__ fp16 g_wo16[E_*E_];
__device__ fp16 g_q16 [B_*H_*N_*HD_];
__device__ fp16 g_k16 [B_*H_*N_*HD_];
__device__ fp16 g_v16 [B_*H_*N_*HD_];
__device__ fp16 g_sa16[M_*E_];

// ---------------- helpers ----------------
__device__ __forceinline__ uint32_t smem_u32(const void* p) {
    uint32_t a;
    asm("{ .reg .u64 t; cvta.to.shared.u64 t, %1; cvt.u32.u64 %0, t; }"
        : "=r"(a) : "l"(p));
    return a;
}
__device__ __forceinline__ void mma_f16(float c[4], const uint32_t a[4],
                                        uint32_t b0, uint32_t b1) {
    asm volatile(
        "mma.sync.aligned.m16n8k16.row.col.f32.f16.f16.f32 "
        "{%0,%1,%2,%3}, {%4,%5,%6,%7}, {%8,%9}, {%0,%1,%2,%3};"
        : "+f"(c[0]), "+f"(c[1]), "+f"(c[2]), "+f"(c[3])
        : "r"(a[0]), "r"(a[1]), "r"(a[2]), "r"(a[3]), "r"(b0), "r"(b1));
}
__device__ __forceinline__ void ldm4(uint32_t r[4], uint32_t addr) {
    asm volatile("ldmatrix.sync.aligned.m8n8.x4.shared.b16 {%0,%1,%2,%3}, [%4];"
                 : "=r"(r[0]), "=r"(r[1]), "=r"(r[2]), "=r"(r[3]) : "r"(addr));
}
__device__ __forceinline__ void ldm4t(uint32_t r[4], uint32_t addr) {
    asm volatile("ldmatrix.sync.aligned.m8n8.x4.trans.shared.b16 {%0,%1,%2,%3}, [%4];"
                 : "=r"(r[0]), "=r"(r[1]), "=r"(r[2]), "=r"(r[3]) : "r"(addr));
}
__device__ __forceinline__ uint32_t pack_f16(float v0, float v1) {
    __half2 h = __floats2half2_rn(v0, v1);
    return *reinterpret_cast<uint32_t*>(&h);
}
#define CP16(d, s)  asm volatile("cp.async.cg.shared.global [%0], [%1], 16;" :: "r"(d), "l"(s))
#define CP_COMMIT() asm volatile("cp.async.commit_group;" ::: "memory")
#define CP_WAIT0()  asm volatile("cp.async.wait_group 0;" ::: "memory")

// ---------------- pre-pass: fp32 -> fp16 ----------------
__global__ void cvt_kernel(const float* __restrict__ src, fp16* __restrict__ dst, int n4)
{
    int i = blockIdx.x * blockDim.x + threadIdx.x;
    int stride = gridDim.x * blockDim.x;
    for (; i < n4; i += stride) {
        float4 v = ((const float4*)src)[i];
        ((uint2*)dst)[i] = make_uint2(pack_f16(v.x, v.y), pack_f16(v.z, v.w));
    }
}

// GEMM smem geometry (per buffer, double buffered), BK=64:
// A @0: 128 rows x pitch 144 (64 fp16 + pad) = 18432
// B @18432: 64 k-rows x pitch 272 (128 fp16 + pad) = 17408
#define GBUF2 35840
#define GEMM_SMEM (2*GBUF2)

// ---------------- kernel 1: QKV projection (fp16 HMMA, BK=64) ----------------
__global__ __launch_bounds__(256, 2) void qkv_mma(const float* __restrict__ bias)
{
    extern __shared__ __align__(16) uint8_t dsm[];
    const uint32_t sb = smem_u32(dsm);
    const int tid = threadIdx.x, lane = tid & 31, wid = tid >> 5;
    const int wm = wid >> 1, wn = wid & 1;
    const int m0 = blockIdx.y * 128, n0 = blockIdx.x * 128;
    const int g = lane >> 2, cq = (lane & 3) * 2;
    const int lrA = (lane & 7) + ((lane >> 3) & 1) * 8, lcA = ((lane >> 4) & 1) * 8;

    const fp16* srcA[4]; uint32_t dstA[4];
    const fp16* srcB[4]; uint32_t dstB[4];
#pragma unroll
    for (int t = 0; t < 4; t++) {
        int j = t * 256 + tid, row = j >> 3, sg = (j & 7) * 8;
        srcA[t] = g_x16 + (size_t)(m0 + row) * E_ + sg;
        dstA[t] = row * 144 + sg * 2;
    }
#pragma unroll
    for (int t = 0; t < 4; t++) {
        int j = t * 256 + tid, k = j >> 4, sg = (j & 15) * 8;
        int col = n0 + sg, hh = col / 192, ff = col - hh * 192;
        srcB[t] = g_wq16 + (size_t)(hh * E_ + k) * 192 + ff;
        dstB[t] = 18432u + k * 272 + sg * 2;
    }

    float acc[2][8][4];
#pragma unroll
    for (int t = 0; t < 2; t++)
#pragma unroll
        for (int nt = 0; nt < 8; nt++)
#pragma unroll
            for (int j = 0; j < 4; j++) acc[t][nt][j] = 0.f;

#pragma unroll
    for (int t = 0; t < 4; t++) CP16(sb + dstA[t], srcA[t]);
#pragma unroll
    for (int t = 0; t < 4; t++) CP16(sb + dstB[t], srcB[t]);
    CP_COMMIT();

    for (int kc = 0; kc < 16; kc++) {
        const uint32_t base = sb + (uint32_t)(kc & 1) * GBUF2;
        CP_WAIT0();
        __syncthreads();
        if (kc < 15) {
            const uint32_t nb = sb + (uint32_t)((kc + 1) & 1) * GBUF2;
#pragma unroll
            for (int t = 0; t < 4; t++) { srcA[t] += 64;       CP16(nb + dstA[t], srcA[t]); }
#pragma unroll
            for (int t = 0; t < 4; t++) { srcB[t] += 64 * 192; CP16(nb + dstB[t], srcB[t]); }
            CP_COMMIT();
        }
#pragma unroll
        for (int kk = 0; kk < 4; kk++) {
            uint32_t af[2][4];
#pragma unroll
            for (int t = 0; t < 2; t++)
                ldm4(af[t], base + (wm * 32 + t * 16 + lrA) * 144 + (kk * 16 + lcA) * 2);
#pragma unroll
            for (int np = 0; np < 4; np++) {
                uint32_t bf[4];
                ldm4t(bf, base + 18432u + (kk * 16 + lrA) * 272
                           + (wn * 64 + np * 16 + lcA) * 2);
#pragma unroll
                for (int t = 0; t < 2; t++)
#pragma unroll
                    for (int j = 0; j < 2; j++)
                        mma_f16(acc[t][np * 2 + j], af[t], bf[j * 2], bf[j * 2 + 1]);
            }
        }
    }

    // epilogue: +bias, fp16 scatter into K/Q/V planes (split order K,Q,V)
#pragma unroll
    for (int t = 0; t < 2; t++)
#pragma unroll
        for (int nt = 0; nt < 8; nt++) {
            int col = n0 + wn * 64 + nt * 8 + cq;
            float b0v = bias[col], b1v = bias[col + 1];
            int hh = col / 192, ff = col - hh * 192;
            int sel = ff >> 6, ffl = ff & 63;
            fp16* ph = (sel == 0) ? g_k16 : (sel == 1) ? g_q16 : g_v16;
#pragma unroll
            for (int rh = 0; rh < 2; rh++) {
                int m = m0 + wm * 32 + t * 16 + g + rh * 8;
                int bb = m >> 11, n = m & (N_ - 1);
                uint32_t hp = pack_f16(acc[t][nt][rh * 2] + b0v,
                                       acc[t][nt][rh * 2 + 1] + b1v);
                size_t idx = ((size_t)(bb * H_ + hh) * N_ + n) * HD_ + ffl;
                *(uint32_t*)(ph + idx) = hp;
            }
        }
}

// ---------------- kernel 2: causal flash attention (fp16 HMMA) --------
// KV buffer: K@0 (64 x pitch144 = 9216), V@9216. ABUF=18432, double buffered.
// Q @36864 (128 x 144 = 18432). Total 55296.
#define ABUF16 18432
#define ATTN_SMEM (2*ABUF16 + 18432)
__global__ __launch_bounds__(256, 2) void attn_mma()
{
    extern __shared__ __align__(16) uint8_t dsm[];
    const uint32_t sb = smem_u32(dsm);
    const int tid = threadIdx.x, lane = tid & 31, w = tid >> 5;
    const int qt = blockIdx.x, bhd = blockIdx.y;
    const int g = lane >> 2, cq = (lane & 3) * 2;
    const int lrA = (lane & 7) + ((lane >> 3) & 1) * 8, lcA = ((lane >> 4) & 1) * 8;
    const int lrB = (lane & 7) + ((lane >> 4) & 1) * 8, lcB = ((lane >> 3) & 1) * 8;
    const uint32_t QB = sb + 2 * ABUF16;

    const fp16* srcKV[4]; uint32_t dstKV[4];
#pragma unroll
    for (int t = 0; t < 4; t++) {
        int j = (t & 1) * 256 + tid, row = j >> 3, sg = (j & 7) * 8;
        srcKV[t] = ((t < 2) ? g_k16 : g_v16) + (size_t)(bhd * N_ + row) * HD_ + sg;
        dstKV[t] = ((t < 2) ? 0u : 9216u) + row * 144 + sg * 2;
    }
#pragma unroll
    for (int t = 0; t < 4; t++) CP16(sb + dstKV[t], srcKV[t]);
    CP_COMMIT();

    // stage Q (128x64 fp16) in smem; frags loaded on demand
#pragma unroll
    for (int t = 0; t < 4; t++) {
        int j = t * 256 + tid, row = j >> 3, sg = (j & 7) * 8;
        uint4 v = ((const uint4*)g_q16)[((size_t)(bhd * N_ + qt * 128 + row) * HD_ + sg) >> 3];
        *(uint4*)((size_t)dsm + (QB - sb) + row * 144 + sg * 2) = v;
    }

    float o[8][4];
#pragma unroll
    for (int nt = 0; nt < 8; nt++)
#pragma unroll
        for (int j = 0; j < 4; j++) o[nt][j] = 0.f;
    float mrow[2] = {-1e30f, -1e30f}, lrow[2] = {0.f, 0.f};
    const int qr0 = qt * 128 + w * 16 + g;
    const int wmaxk = qt * 128 + w * 16 + 15;
    const int ktmax = 2 * qt + 1;

    for (int kt = 0; kt <= ktmax; kt++) {
        const uint32_t base = sb + (uint32_t)(kt & 1) * ABUF16;
        CP_WAIT0();
        __syncthreads();
        if (kt < ktmax) {
            const uint32_t nb = sb + (uint32_t)((kt + 1) & 1) * ABUF16;
#pragma unroll
            for (int t = 0; t < 4; t++) { srcKV[t] += 64 * HD_; CP16(nb + dstKV[t], srcKV[t]); }
            CP_COMMIT();
        }
        if (kt * 64 <= wmaxk) {
            const uint32_t KB = base, VB = base + 9216;
            float s_[8][4];
#pragma unroll
            for (int nt = 0; nt < 8; nt++)
#pragma unroll
                for (int j = 0; j < 4; j++) s_[nt][j] = 0.f;
#pragma unroll
            for (int kk = 0; kk < 4; kk++) {
                uint32_t qf[4];
                ldm4(qf, QB + (w * 16 + lrA) * 144 + (kk * 16 + lcA) * 2);
#pragma unroll
                for (int np = 0; np < 4; np++) {
                    uint32_t kf[4];
                    ldm4(kf, KB + (np * 16 + lrB) * 144 + (kk * 16 + lcB) * 2);
#pragma unroll
                    for (int j = 0; j < 2; j++)
                        mma_f16(s_[np * 2 + j], qf, kf[j * 2], kf[j * 2 + 1]);
                }
            }
            // scale + causal mask
            const int kbase = kt * 64;
#pragma unroll
            for (int nt = 0; nt < 8; nt++)
#pragma unroll
                for (int j = 0; j < 4; j++) {
                    float sv = s_[nt][j] * 0.125f;
                    int colg = kbase + nt * 8 + cq + (j & 1);
                    int rowg = (j < 2) ? qr0 : qr0 + 8;
                    if (colg > rowg) sv = -1e30f;
                    s_[nt][j] = sv;
                }
            // online softmax (quad reduction over lane&3)
#pragma unroll
            for (int a = 0; a < 2; a++) {
                float tm = -1e30f;
#pragma unroll
                for (int nt = 0; nt < 8; nt++)
                    tm = fmaxf(tm, fmaxf(s_[nt][a * 2], s_[nt][a * 2 + 1]));
                tm = fmaxf(tm, __shfl_xor_sync(0xffffffffu, tm, 1));
                tm = fmaxf(tm, __shfl_xor_sync(0xffffffffu, tm, 2));
                float mn = fmaxf(mrow[a], tm);
                float alpha = __expf(mrow[a] - mn);
                float rs = 0.f;
#pragma unroll
                for (int nt = 0; nt < 8; nt++)
#pragma unroll
                    for (int jj = 0; jj < 2; jj++) {
                        float p = __expf(s_[nt][a * 2 + jj] - mn);
                        s_[nt][a * 2 + jj] = p;
                        rs += p;
                    }
                rs += __shfl_xor_sync(0xffffffffu, rs, 1);
                rs += __shfl_xor_sync(0xffffffffu, rs, 2);
                lrow[a] = lrow[a] * alpha + rs;
                mrow[a] = mn;
#pragma unroll
                for (int nt = 0; nt < 8; nt++) {
                    o[nt][a * 2]     *= alpha;
                    o[nt][a * 2 + 1] *= alpha;
                }
            }
            // O += P V; P a-frags packed from s_ c-frags
#pragma unroll
            for (int kk = 0; kk < 4; kk++) {
                uint32_t pa[4];
                pa[0] = pack_f16(s_[2 * kk][0],     s_[2 * kk][1]);
                pa[1] = pack_f16(s_[2 * kk][2],     s_[2 * kk][3]);
                pa[2] = pack_f16(s_[2 * kk + 1][0], s_[2 * kk + 1][1]);
                pa[3] = pack_f16(s_[2 * kk + 1][2], s_[2 * kk + 1][3]);
#pragma unroll
                for (int np = 0; np < 4; np++) {
                    uint32_t vf[4];
                    ldm4t(vf, VB + (kk * 16 + lrA) * 144 + (np * 16 + lcA) * 2);
#pragma unroll
                    for (int j = 0; j < 2; j++)
                        mma_f16(o[np * 2 + j], pa, vf[j * 2], vf[j * 2 + 1]);
                }
            }
        }
    }

    // epilogue: O/l -> fp16 sa [B,N,E]
    const int bb = bhd >> 4, hh = bhd & 15;
    float inv[2] = {1.f / lrow[0], 1.f / lrow[1]};
#pragma unroll
    for (int nt = 0; nt < 8; nt++) {
        int d = hh * 64 + nt * 8 + cq;
#pragma unroll
        for (int a = 0; a < 2; a++) {
            int n = qt * 128 + w * 16 + g + a * 8;
            uint32_t hp = pack_f16(o[nt][a * 2] * inv[a], o[nt][a * 2 + 1] * inv[a]);
            *(uint32_t*)(g_sa16 + (size_t)(bb * N_ + n) * E_ + d) = hp;
        }
    }
}

// ---------------- kernel 3: output projection (fp16 HMMA, BK=64) --------------
__global__ __launch_bounds__(256, 2) void out_mma(const float* __restrict__ bias,
                                                  float* __restrict__ out)
{
    extern __shared__ __align__(16) uint8_t dsm[];
    const uint32_t sb = smem_u32(dsm);
    const int tid = threadIdx.x, lane = tid & 31, wid = tid >> 5;
    const int wm = wid >> 1, wn = wid & 1;
    const int m0 = blockIdx.y * 128, n0 = blockIdx.x * 128;
    const int g = lane >> 2, cq = (lane & 3) * 2;
    const int lrA = (lane & 7) + ((lane >> 3) & 1) * 8, lcA = ((lane >> 4) & 1) * 8;

    const fp16* srcA[4]; uint32_t dstA[4];
    const fp16* srcB[4]; uint32_t dstB[4];
#pragma unroll
    for (int t = 0; t < 4; t++) {
        int j = t * 256 + tid, row = j >> 3, sg = (j & 7) * 8;
        srcA[t] = g_sa16 + (size_t)(m0 + row) * E_ + sg;
        dstA[t] = row * 144 + sg * 2;
    }
#pragma unroll
    for (int t = 0; t < 4; t++) {
        int j = t * 256 + tid, k = j >> 4, sg = (j & 15) * 8;
        srcB[t] = g_wo16 + (size_t)k * E_ + n0 + sg;
        dstB[t] = 18432u + k * 272 + sg * 2;
    }

    float acc[2][8][4];
#pragma unroll
    for (int t = 0; t < 2; t++)
#pragma unroll
        for (int nt = 0; nt < 8; nt++)
#pragma unroll
            for (int j = 0; j < 4; j++) acc[t][nt][j] = 0.f;

#pragma unroll
    for (int t = 0; t < 4; t++) CP16(sb + dstA[t], srcA[t]);
#pragma unroll
    for (int t = 0; t < 4; t++) CP16(sb + dstB[t], srcB[t]);
    CP_COMMIT();

    for (int kc = 0; kc < 16; kc++) {
        const uint32_t base = sb + (uint32_t)(kc & 1) * GBUF2;
        CP_WAIT0();
        __syncthreads();
        if (kc < 15) {
            const uint32_t nb = sb + (uint32_t)((kc + 1) & 1) * GBUF2;
#pragma unroll
            for (int t = 0; t < 4; t++) { srcA[t] += 64;      CP16(nb + dstA[t], srcA[t]); }
#pragma unroll
            for (int t = 0; t < 4; t++) { srcB[t] += 64 * E_; CP16(nb + dstB[t], srcB[t]); }
            CP_COMMIT();
        }
#pragma unroll
        for (int kk = 0; kk < 4; kk++) {
            uint32_t af[2][4];
#pragma unroll
            for (int t = 0; t < 2; t++)
                ldm4(af[t], base + (wm * 32 + t * 16 + lrA) * 144 + (kk * 16 + lcA) * 2);
#pragma unroll
            for (int np = 0; np < 4; np++) {
                uint32_t bf[4];
                ldm4t(bf, base + 18432u + (kk * 16 + lrA) * 272
                           + (wn * 64 + np * 16 + lcA) * 2);
#pragma unroll
                for (int t = 0; t < 2; t++)
#pragma unroll
                    for (int j = 0; j < 2; j++)
                        mma_f16(acc[t][np * 2 + j], af[t], bf[j * 2], bf[j * 2 + 1]);
            }
        }
    }

#pragma unroll
    for (int t = 0; t < 2; t++)
#pragma unroll
        for (int nt = 0; nt < 8; nt++) {
            int col = n0 + wn * 64 + nt * 8 + cq;
            float b0v = bias[col], b1v = bias[col + 1];
#pragma unroll
            for (int rh = 0; rh < 2; rh++) {
                int m = m0 + wm * 32 + t * 16 + g + rh * 8;
                float2 v;
                v.x = acc[t][nt][rh * 2 + 0] + b0v;
                v.y = acc[t][nt][rh * 2 + 1] + b1v;
                *(float2*)(out + (size_t)m * E_ + col) = v;
            }
        }
}

// ---------------------------------------------------------------------------
extern "C" void kernel_launch(void* const* d_in, const int* in_sizes, int n_in,
                              void* d_out, int out_size)
{
    const float* x    = (const float*)d_in[0];   // [B,N,E]
    const float* Wqkv = (const float*)d_in[1];   // [H,E,192]
    const float* bqkv = (const float*)d_in[2];   // [H,192]
    const float* Wout = (const float*)d_in[3];   // [E,E]
    const float* bout = (const float*)d_in[4];   // [E]
    float* out = (float*)d_out;                  // [B,N,E]

    static int configured = 0;
    if (!configured) {
        cudaFuncSetAttribute(qkv_mma,  cudaFuncAttributeMaxDynamicSharedMemorySize, GEMM_SMEM);
        cudaFuncSetAttribute(out_mma,  cudaFuncAttributeMaxDynamicSharedMemorySize, GEMM_SMEM);
        cudaFuncSetAttribute(attn_mma, cudaFuncAttributeMaxDynamicSharedMemorySize, ATTN_SMEM);
        configured = 1;
    }

    fp16 *x16, *wq16, *wo16;
    cudaGetSymbolAddress((void**)&x16,  g_x16);
    cudaGetSymbolAddress((void**)&wq16, g_wq16);
    cudaGetSymbolAddress((void**)&wo16, g_wo16);

    cvt_kernel<<<1024, 256>>>(x,    x16,  (M_ * E_) / 4);
    cvt_kernel<<<1024, 256>>>(Wqkv, wq16, (H_ * E_ * 192) / 4);
    cvt_kernel<<<1024, 256>>>(Wout, wo16, (E_ * E_) / 4);

    dim3 g1(QKVC / 128, M_ / 128);   // 24 x 32
    qkv_mma<<<g1, 256, GEMM_SMEM>>>(bqkv);

    dim3 g2(N_ / 128, B_ * H_);      // 16 x 32
    attn_mma<<<g2, 256, ATTN_SMEM>>>();

    dim3 g3(E_ / 128, M_ / 128);     // 8 x 32
    out_mma<<<g3, 256, GEMM_SMEM>>>(bout, out);
}

// round 7
// speedup vs baseline: 8.7550x; 1.0289x over previous
#include <cuda_runtime.h>
#include <cuda_fp16.h>
#include <cstdint>

#define B_   2
#define N_   2048
#define E_   1024
#define H_   16
#define HD_  64
#define M_   (B_*N_)        // 4096
#define QKVC (H_*3*HD_)     // 3072

typedef __half fp16;

// ---------------- scratch (static __device__, no allocs) ----------------
__device__ fp16 g_x16 [M_*E_];
__device__ fp16 g_wq16[H_*E_*192];
__device__ fp16 g_wo16[E_*E_];
__device__ fp16 g_q16 [B_*H_*N_*HD_];   // pre-scaled by 1/sqrt(HD)
__device__ fp16 g_k16 [B_*H_*N_*HD_];
__device__ fp16 g_v16 [B_*H_*N_*HD_];
__device__ fp16 g_sa16[M_*E_];

// ---------------- helpers ----------------
__device__ __forceinline__ uint32_t smem_u32(const void* p) {
    uint32_t a;
    asm("{ .reg .u64 t; cvta.to.shared.u64 t, %1; cvt.u32.u64 %0, t; }"
        : "=r"(a) : "l"(p));
    return a;
}
__device__ __forceinline__ void mma_f16(float c[4], const uint32_t a[4],
                                        uint32_t b0, uint32_t b1) {
    asm volatile(
        "mma.sync.aligned.m16n8k16.row.col.f32.f16.f16.f32 "
        "{%0,%1,%2,%3}, {%4,%5,%6,%7}, {%8,%9}, {%0,%1,%2,%3};"
        : "+f"(c[0]), "+f"(c[1]), "+f"(c[2]), "+f"(c[3])
        : "r"(a[0]), "r"(a[1]), "r"(a[2]), "r"(a[3]), "r"(b0), "r"(b1));
}
__device__ __forceinline__ void ldm4(uint32_t r[4], uint32_t addr) {
    asm volatile("ldmatrix.sync.aligned.m8n8.x4.shared.b16 {%0,%1,%2,%3}, [%4];"
                 : "=r"(r[0]), "=r"(r[1]), "=r"(r[2]), "=r"(r[3]) : "r"(addr));
}
__device__ __forceinline__ void ldm4t(uint32_t r[4], uint32_t addr) {
    asm volatile("ldmatrix.sync.aligned.m8n8.x4.trans.shared.b16 {%0,%1,%2,%3}, [%4];"
                 : "=r"(r[0]), "=r"(r[1]), "=r"(r[2]), "=r"(r[3]) : "r"(addr));
}
__device__ __forceinline__ uint32_t pack_f16(float v0, float v1) {
    __half2 h = __floats2half2_rn(v0, v1);
    return *reinterpret_cast<uint32_t*>(&h);
}
#define CP16(d, s)  asm volatile("cp.async.cg.shared.global [%0], [%1], 16;" :: "r"(d), "l"(s))
#define CP_COMMIT() asm volatile("cp.async.commit_group;" ::: "memory")
#define CP_WAIT0()  asm volatile("cp.async.wait_group 0;" ::: "memory")

// ---------------- pre-pass: fp32 -> fp16 (all three tensors, one launch) ------
#define C1 ((M_*E_)/4)
#define C2 ((H_*E_*192)/4)
#define C3 ((E_*E_)/4)
__global__ void cvt_all(const float* __restrict__ x, const float* __restrict__ wq,
                        const float* __restrict__ wo)
{
    int i = blockIdx.x * blockDim.x + threadIdx.x;
    int stride = gridDim.x * blockDim.x;
    for (; i < C1 + C2 + C3; i += stride) {
        const float4* s; uint2* d; int j;
        if (i < C1)           { s = (const float4*)x;  d = (uint2*)g_x16;  j = i; }
        else if (i < C1 + C2) { s = (const float4*)wq; d = (uint2*)g_wq16; j = i - C1; }
        else                  { s = (const float4*)wo; d = (uint2*)g_wo16; j = i - C1 - C2; }
        float4 v = s[j];
        d[j] = make_uint2(pack_f16(v.x, v.y), pack_f16(v.z, v.w));
    }
}

// GEMM smem geometry (per buffer, double buffered), BK=64:
// A @0: 128 rows x pitch 144; B @18432: 64 k-rows x pitch 272
#define GBUF2 35840
#define GEMM_SMEM (2*GBUF2)

// ---------------- kernel 1: QKV projection (fp16 HMMA, BK=64) ----------------
__global__ __launch_bounds__(256, 2) void qkv_mma(const float* __restrict__ bias)
{
    extern __shared__ __align__(16) uint8_t dsm[];
    const uint32_t sb = smem_u32(dsm);
    const int tid = threadIdx.x, lane = tid & 31, wid = tid >> 5;
    const int wm = wid >> 1, wn = wid & 1;
    const int m0 = blockIdx.y * 128, n0 = blockIdx.x * 128;
    const int g = lane >> 2, cq = (lane & 3) * 2;
    const int lrA = (lane & 7) + ((lane >> 3) & 1) * 8, lcA = ((lane >> 4) & 1) * 8;

    const fp16* srcA[4]; uint32_t dstA[4];
    const fp16* srcB[4]; uint32_t dstB[4];
#pragma unroll
    for (int t = 0; t < 4; t++) {
        int j = t * 256 + tid, row = j >> 3, sg = (j & 7) * 8;
        srcA[t] = g_x16 + (size_t)(m0 + row) * E_ + sg;
        dstA[t] = row * 144 + sg * 2;
    }
#pragma unroll
    for (int t = 0; t < 4; t++) {
        int j = t * 256 + tid, k = j >> 4, sg = (j & 15) * 8;
        int col = n0 + sg, hh = col / 192, ff = col - hh * 192;
        srcB[t] = g_wq16 + (size_t)(hh * E_ + k) * 192 + ff;
        dstB[t] = 18432u + k * 272 + sg * 2;
    }

    float acc[2][8][4];
#pragma unroll
    for (int t = 0; t < 2; t++)
#pragma unroll
        for (int nt = 0; nt < 8; nt++)
#pragma unroll
            for (int j = 0; j < 4; j++) acc[t][nt][j] = 0.f;

#pragma unroll
    for (int t = 0; t < 4; t++) CP16(sb + dstA[t], srcA[t]);
#pragma unroll
    for (int t = 0; t < 4; t++) CP16(sb + dstB[t], srcB[t]);
    CP_COMMIT();

    for (int kc = 0; kc < 16; kc++) {
        const uint32_t base = sb + (uint32_t)(kc & 1) * GBUF2;
        CP_WAIT0();
        __syncthreads();
        if (kc < 15) {
            const uint32_t nb = sb + (uint32_t)((kc + 1) & 1) * GBUF2;
#pragma unroll
            for (int t = 0; t < 4; t++) { srcA[t] += 64;       CP16(nb + dstA[t], srcA[t]); }
#pragma unroll
            for (int t = 0; t < 4; t++) { srcB[t] += 64 * 192; CP16(nb + dstB[t], srcB[t]); }
            CP_COMMIT();
        }
#pragma unroll
        for (int kk = 0; kk < 4; kk++) {
            uint32_t af[2][4];
#pragma unroll
            for (int t = 0; t < 2; t++)
                ldm4(af[t], base + (wm * 32 + t * 16 + lrA) * 144 + (kk * 16 + lcA) * 2);
#pragma unroll
            for (int np = 0; np < 4; np++) {
                uint32_t bf[4];
                ldm4t(bf, base + 18432u + (kk * 16 + lrA) * 272
                           + (wn * 64 + np * 16 + lcA) * 2);
#pragma unroll
                for (int t = 0; t < 2; t++)
#pragma unroll
                    for (int j = 0; j < 2; j++)
                        mma_f16(acc[t][np * 2 + j], af[t], bf[j * 2], bf[j * 2 + 1]);
            }
        }
    }

    // epilogue: +bias, fp16 scatter into K/Q/V planes (split order K,Q,V);
    // Q is pre-scaled by 1/sqrt(HD)=0.125 here so attn skips the scale.
#pragma unroll
    for (int t = 0; t < 2; t++)
#pragma unroll
        for (int nt = 0; nt < 8; nt++) {
            int col = n0 + wn * 64 + nt * 8 + cq;
            float b0v = bias[col], b1v = bias[col + 1];
            int hh = col / 192, ff = col - hh * 192;
            int sel = ff >> 6, ffl = ff & 63;
            fp16* ph = (sel == 0) ? g_k16 : (sel == 1) ? g_q16 : g_v16;
            float scale = (sel == 1) ? 0.125f : 1.0f;
#pragma unroll
            for (int rh = 0; rh < 2; rh++) {
                int m = m0 + wm * 32 + t * 16 + g + rh * 8;
                int bb = m >> 11, n = m & (N_ - 1);
                uint32_t hp = pack_f16((acc[t][nt][rh * 2] + b0v) * scale,
                                       (acc[t][nt][rh * 2 + 1] + b1v) * scale);
                size_t idx = ((size_t)(bb * H_ + hh) * N_ + n) * HD_ + ffl;
                *(uint32_t*)(ph + idx) = hp;
            }
        }
}

// ---------------- kernel 2: causal flash attention (fp16 HMMA, fp16x2 exp2) ---
// KV buffer: K@0 (64 x pitch144 = 9216), V@9216. ABUF=18432, double buffered.
// Q @36864 (128 x 144 = 18432). Total 55296.
#define ABUF16 18432
#define ATTN_SMEM (2*ABUF16 + 18432)
__global__ __launch_bounds__(256, 2) void attn_mma()
{
    extern __shared__ __align__(16) uint8_t dsm[];
    const uint32_t sb = smem_u32(dsm);
    const int tid = threadIdx.x, lane = tid & 31, w = tid >> 5;
    const int qt = (int)gridDim.x - 1 - (int)blockIdx.x;   // big tiles first
    const int bhd = blockIdx.y;
    const int g = lane >> 2, cq = (lane & 3) * 2;
    const int lrA = (lane & 7) + ((lane >> 3) & 1) * 8, lcA = ((lane >> 4) & 1) * 8;
    const int lrB = (lane & 7) + ((lane >> 4) & 1) * 8, lcB = ((lane >> 3) & 1) * 8;
    const uint32_t QB = sb + 2 * ABUF16;
    const float L2E = 1.4426950408889634f;

    const fp16* srcKV[4]; uint32_t dstKV[4];
#pragma unroll
    for (int t = 0; t < 4; t++) {
        int j = (t & 1) * 256 + tid, row = j >> 3, sg = (j & 7) * 8;
        srcKV[t] = ((t < 2) ? g_k16 : g_v16) + (size_t)(bhd * N_ + row) * HD_ + sg;
        dstKV[t] = ((t < 2) ? 0u : 9216u) + row * 144 + sg * 2;
    }
#pragma unroll
    for (int t = 0; t < 4; t++) CP16(sb + dstKV[t], srcKV[t]);
    CP_COMMIT();

    // stage Q (128x64 fp16, pre-scaled) in smem; frags loaded on demand
#pragma unroll
    for (int t = 0; t < 4; t++) {
        int j = t * 256 + tid, row = j >> 3, sg = (j & 7) * 8;
        uint4 v = ((const uint4*)g_q16)[((size_t)(bhd * N_ + qt * 128 + row) * HD_ + sg) >> 3];
        *(uint4*)((size_t)dsm + (QB - sb) + row * 144 + sg * 2) = v;
    }

    float o[8][4];
#pragma unroll
    for (int nt = 0; nt < 8; nt++)
#pragma unroll
        for (int j = 0; j < 4; j++) o[nt][j] = 0.f;
    float mrow[2] = {-1e30f, -1e30f}, lrow[2] = {0.f, 0.f};
    const int qr0 = qt * 128 + w * 16 + g;
    const int wmaxk = qt * 128 + w * 16 + 15;
    const int ktmax = 2 * qt + 1;

    for (int kt = 0; kt <= ktmax; kt++) {
        const uint32_t base = sb + (uint32_t)(kt & 1) * ABUF16;
        CP_WAIT0();
        __syncthreads();
        if (kt < ktmax) {
            const uint32_t nb = sb + (uint32_t)((kt + 1) & 1) * ABUF16;
#pragma unroll
            for (int t = 0; t < 4; t++) { srcKV[t] += 64 * HD_; CP16(nb + dstKV[t], srcKV[t]); }
            CP_COMMIT();
        }
        if (kt * 64 <= wmaxk) {
            const uint32_t KB = base, VB = base + 9216;
            float s_[8][4];
#pragma unroll
            for (int nt = 0; nt < 8; nt++)
#pragma unroll
                for (int j = 0; j < 4; j++) s_[nt][j] = 0.f;
#pragma unroll
            for (int kk = 0; kk < 4; kk++) {
                uint32_t qf[4];
                ldm4(qf, QB + (w * 16 + lrA) * 144 + (kk * 16 + lcA) * 2);
#pragma unroll
                for (int np = 0; np < 4; np++) {
                    uint32_t kf[4];
                    ldm4(kf, KB + (np * 16 + lrB) * 144 + (kk * 16 + lcB) * 2);
#pragma unroll
                    for (int j = 0; j < 2; j++)
                        mma_f16(s_[np * 2 + j], qf, kf[j * 2], kf[j * 2 + 1]);
                }
            }
            // causal mask (Q already scaled)
            const int kbase = kt * 64;
#pragma unroll
            for (int nt = 0; nt < 8; nt++)
#pragma unroll
                for (int j = 0; j < 4; j++) {
                    int colg = kbase + nt * 8 + cq + (j & 1);
                    int rowg = (j < 2) ? qr0 : qr0 + 8;
                    if (colg > rowg) s_[nt][j] = -1e30f;
                }
            // online softmax; P computed as fp16x2 via ex2.approx.f16x2, stored
            // back into s_ slots [0]/[2] as packed half2 (rows g / g+8).
#pragma unroll
            for (int a = 0; a < 2; a++) {
                float tm = -1e30f;
#pragma unroll
                for (int nt = 0; nt < 8; nt++)
                    tm = fmaxf(tm, fmaxf(s_[nt][a * 2], s_[nt][a * 2 + 1]));
                tm = fmaxf(tm, __shfl_xor_sync(0xffffffffu, tm, 1));
                tm = fmaxf(tm, __shfl_xor_sync(0xffffffffu, tm, 2));
                float mn = fmaxf(mrow[a], tm);
                float alpha = __expf(mrow[a] - mn);
                float mnl = mn * L2E;
                float rs = 0.f;
#pragma unroll
                for (int nt = 0; nt < 8; nt++) {
                    float e0 = __fmaf_rn(s_[nt][a * 2],     L2E, -mnl);
                    float e1 = __fmaf_rn(s_[nt][a * 2 + 1], L2E, -mnl);
                    __half2 h = h2exp2(__floats2half2_rn(e0, e1));
                    float2 pf = __half22float2(h);
                    rs += pf.x + pf.y;
                    s_[nt][a * 2] = __uint_as_float(*reinterpret_cast<uint32_t*>(&h));
                }
                rs += __shfl_xor_sync(0xffffffffu, rs, 1);
                rs += __shfl_xor_sync(0xffffffffu, rs, 2);
                lrow[a] = lrow[a] * alpha + rs;
                mrow[a] = mn;
#pragma unroll
                for (int nt = 0; nt < 8; nt++) {
                    o[nt][a * 2]     *= alpha;
                    o[nt][a * 2 + 1] *= alpha;
                }
            }
            // O += P V; P a-frags are the packed half2 bits already in s_
#pragma unroll
            for (int kk = 0; kk < 4; kk++) {
                uint32_t pa[4];
                pa[0] = __float_as_uint(s_[2 * kk][0]);
                pa[1] = __float_as_uint(s_[2 * kk][2]);
                pa[2] = __float_as_uint(s_[2 * kk + 1][0]);
                pa[3] = __float_as_uint(s_[2 * kk + 1][2]);
#pragma unroll
                for (int np = 0; np < 4; np++) {
                    uint32_t vf[4];
                    ldm4t(vf, VB + (kk * 16 + lrA) * 144 + (np * 16 + lcA) * 2);
#pragma unroll
                    for (int j = 0; j < 2; j++)
                        mma_f16(o[np * 2 + j], pa, vf[j * 2], vf[j * 2 + 1]);
                }
            }
        }
    }

    // epilogue: O/l -> fp16 sa [B,N,E]
    const int bb = bhd >> 4, hh = bhd & 15;
    float inv[2] = {1.f / lrow[0], 1.f / lrow[1]};
#pragma unroll
    for (int nt = 0; nt < 8; nt++) {
        int d = hh * 64 + nt * 8 + cq;
#pragma unroll
        for (int a = 0; a < 2; a++) {
            int n = qt * 128 + w * 16 + g + a * 8;
            uint32_t hp = pack_f16(o[nt][a * 2] * inv[a], o[nt][a * 2 + 1] * inv[a]);
            *(uint32_t*)(g_sa16 + (size_t)(bb * N_ + n) * E_ + d) = hp;
        }
    }
}

// ---------------- kernel 3: output projection (fp16 HMMA, BK=64) --------------
__global__ __launch_bounds__(256, 2) void out_mma(const float* __restrict__ bias,
                                                  float* __restrict__ out)
{
    extern __shared__ __align__(16) uint8_t dsm[];
    const uint32_t sb = smem_u32(dsm);
    const int tid = threadIdx.x, lane = tid & 31, wid = tid >> 5;
    const int wm = wid >> 1, wn = wid & 1;
    const int m0 = blockIdx.y * 128, n0 = blockIdx.x * 128;
    const int g = lane >> 2, cq = (lane & 3) * 2;
    const int lrA = (lane & 7) + ((lane >> 3) & 1) * 8, lcA = ((lane >> 4) & 1) * 8;

    const fp16* srcA[4]; uint32_t dstA[4];
    const fp16* srcB[4]; uint32_t dstB[4];
#pragma unroll
    for (int t = 0; t < 4; t++) {
        int j = t * 256 + tid, row = j >> 3, sg = (j & 7) * 8;
        srcA[t] = g_sa16 + (size_t)(m0 + row) * E_ + sg;
        dstA[t] = row * 144 + sg * 2;
    }
#pragma unroll
    for (int t = 0; t < 4; t++) {
        int j = t * 256 + tid, k = j >> 4, sg = (j & 15) * 8;
        srcB[t] = g_wo16 + (size_t)k * E_ + n0 + sg;
        dstB[t] = 18432u + k * 272 + sg * 2;
    }

    float acc[2][8][4];
#pragma unroll
    for (int t = 0; t < 2; t++)
#pragma unroll
        for (int nt = 0; nt < 8; nt++)
#pragma unroll
            for (int j = 0; j < 4; j++) acc[t][nt][j] = 0.f;

#pragma unroll
    for (int t = 0; t < 4; t++) CP16(sb + dstA[t], srcA[t]);
#pragma unroll
    for (int t = 0; t < 4; t++) CP16(sb + dstB[t], srcB[t]);
    CP_COMMIT();

    for (int kc = 0; kc < 16; kc++) {
        const uint32_t base = sb + (uint32_t)(kc & 1) * GBUF2;
        CP_WAIT0();
        __syncthreads();
        if (kc < 15) {
            const uint32_t nb = sb + (uint32_t)((kc + 1) & 1) * GBUF2;
#pragma unroll
            for (int t = 0; t < 4; t++) { srcA[t] += 64;      CP16(nb + dstA[t], srcA[t]); }
#pragma unroll
            for (int t = 0; t < 4; t++) { srcB[t] += 64 * E_; CP16(nb + dstB[t], srcB[t]); }
            CP_COMMIT();
        }
#pragma unroll
        for (int kk = 0; kk < 4; kk++) {
            uint32_t af[2][4];
#pragma unroll
            for (int t = 0; t < 2; t++)
                ldm4(af[t], base + (wm * 32 + t * 16 + lrA) * 144 + (kk * 16 + lcA) * 2);
#pragma unroll
            for (int np = 0; np < 4; np++) {
                uint32_t bf[4];
                ldm4t(bf, base + 18432u + (kk * 16 + lrA) * 272
                           + (wn * 64 + np * 16 + lcA) * 2);
#pragma unroll
                for (int t = 0; t < 2; t++)
#pragma unroll
                    for (int j = 0; j < 2; j++)
                        mma_f16(acc[t][np * 2 + j], af[t], bf[j * 2], bf[j * 2 + 1]);
            }
        }
    }

#pragma unroll
    for (int t = 0; t < 2; t++)
#pragma unroll
        for (int nt = 0; nt < 8; nt++) {
            int col = n0 + wn * 64 + nt * 8 + cq;
            float b0v = bias[col], b1v = bias[col + 1];
#pragma unroll
            for (int rh = 0; rh < 2; rh++) {
                int m = m0 + wm * 32 + t * 16 + g + rh * 8;
                float2 v;
                v.x = acc[t][nt][rh * 2 + 0] + b0v;
                v.y = acc[t][nt][rh * 2 + 1] + b1v;
                *(float2*)(out + (size_t)m * E_ + col) = v;
            }
        }
}

// ---------------------------------------------------------------------------
extern "C" void kernel_launch(void* const* d_in, const int* in_sizes, int n_in,
                              void* d_out, int out_size)
{
    const float* x    = (const float*)d_in[0];   // [B,N,E]
    const float* Wqkv = (const float*)d_in[1];   // [H,E,192]
    const float* bqkv = (const float*)d_in[2];   // [H,192]
    const float* Wout = (const float*)d_in[3];   // [E,E]
    const float* bout = (const float*)d_in[4];   // [E]
    float* out = (float*)d_out;                  // [B,N,E]

    static int configured = 0;
    if (!configured) {
        cudaFuncSetAttribute(qkv_mma,  cudaFuncAttributeMaxDynamicSharedMemorySize, GEMM_SMEM);
        cudaFuncSetAttribute(out_mma,  cudaFuncAttributeMaxDynamicSharedMemorySize, GEMM_SMEM);
        cudaFuncSetAttribute(attn_mma, cudaFuncAttributeMaxDynamicSharedMemorySize, ATTN_SMEM);
        configured = 1;
    }

    cvt_all<<<2048, 256>>>(x, Wqkv, Wout);

    dim3 g1(QKVC / 128, M_ / 128);   // 24 x 32
    qkv_mma<<<g1, 256, GEMM_SMEM>>>(bqkv);

    dim3 g2(N_ / 128, B_ * H_);      // 16 x 32
    attn_mma<<<g2, 256, ATTN_SMEM>>>();

    dim3 g3(E_ / 128, M_ / 128);     // 8 x 32
    out_mma<<<g3, 256, GEMM_SMEM>>>(bout, out);
}